// round 13
// baseline (speedup 1.0000x reference)
#include <cuda_runtime.h>
#include <cuda_bf16.h>
#include <math.h>
#include <stdint.h>

#define N0 4096
#define CH 256
#define EMAX 131072

using bf16 = __nv_bfloat16;

// ---------------- scratch ----------------
__device__ bf16  g_A1[2048 * 2048];
__device__ bf16  g_A2[1024 * 1024];
__device__ bf16  g_A3[512 * 512];
__device__ bf16  g_AT1[2048 * 2048];
__device__ bf16  g_AT2[1024 * 1024];
__device__ bf16  g_AT3[512 * 512];
__device__ float g_A1f[2048 * 2048];   // augment split-K slices
__device__ float g_X0[N0 * CH];
__device__ float g_X1[2048 * CH];
__device__ float g_X2[1024 * CH];
__device__ float g_Xc[N0 * CH];
__device__ float g_z[N0 * CH];
__device__ bf16  g_WH[7 * 65536];
__device__ bf16  g_WL[7 * 65536];
__device__ bf16  g_zhi[CH * N0];
__device__ bf16  g_zlo[CH * N0];
__device__ float g_Cpart[8 * 2048 * CH];
__device__ int   g_zblk[7 * N0];       // [cnt: 3*N0 | deg: 4*N0(as float)]
__device__ float g_dinv0[N0];
__device__ float g_fil0[N0];
__device__ float g_s[N0];
__device__ float g_pns[3];
__device__ int   g_perm[3][2048];
__device__ int   g_colmap[3][N0];
__device__ int g_rpi[N0 + 1], g_rpo[N0 + 1];
__device__ int g_cii[EMAX], g_cio[EMAX];
__device__ int g_curi[N0], g_curo[N0];
__device__ float g_mpart[32 * 256];

static inline int cdiv(int a, int b) { return (a + b - 1) / b; }

// ---------------- CSR build ----------------
__global__ void count_deg(const int* __restrict__ ei, int E, int* __restrict__ cnt) {
    int i = blockIdx.x * blockDim.x + threadIdx.x;
    if (i >= E) return;
    int s = ei[i], d = ei[E + i];
    atomicAdd(cnt + N0 + s, 1);
    atomicAdd(cnt + d, 1);
    if (s == d) atomicAdd(cnt + 2 * N0 + s, 1);
}

__device__ void scan4096(const int* __restrict__ cnt, int* __restrict__ rp,
                         int* __restrict__ cur, int* loc) {
    int t = threadIdx.x;
    int base = t * 4;
    int v0 = cnt[base], v1 = cnt[base + 1], v2 = cnt[base + 2], v3 = cnt[base + 3];
    int s01 = v0 + v1;
    int s = s01 + v2 + v3;
    loc[t] = s;
    __syncthreads();
    for (int o = 1; o < 1024; o <<= 1) {
        int x = (t >= o) ? loc[t - o] : 0;
        __syncthreads();
        loc[t] += x;
        __syncthreads();
    }
    int excl = loc[t] - s;
    rp[base] = excl;           cur[base] = excl;
    rp[base + 1] = excl + v0;  cur[base + 1] = excl + v0;
    rp[base + 2] = excl + s01; cur[base + 2] = excl + s01;
    rp[base + 3] = excl + s01 + v2; cur[base + 3] = excl + s01 + v2;
    if (t == 1023) rp[4096] = excl + s;
}

__global__ void scan_build(const int* __restrict__ cnt,
                           int* rpi, int* rpo, int* curi, int* curo,
                           float* __restrict__ dinv, float* __restrict__ fil,
                           const float* __restrict__ p_at, float* __restrict__ pns) {
    __shared__ int loc[1024];
    scan4096(cnt, rpi, curi, loc);
    __syncthreads();
    scan4096(cnt + N0, rpo, curo, loc);
    int t = threadIdx.x;
#pragma unroll
    for (int q = 0; q < 4; q++) {
        int c = t * 4 + q;
        float f = (cnt[2 * N0 + c] == 0) ? 2.f : 0.f;
        fil[c] = f;
        dinv[c] = rsqrtf((float)cnt[c] + f);
    }
    if (t < 96) {
        int w = t >> 5, lane = t & 31;
        float a = 0.f;
#pragma unroll
        for (int q = 0; q < 8; q++) {
            float v = p_at[w * 256 + lane + 32 * q];
            a += v * v;
        }
#pragma unroll
        for (int o = 16; o; o >>= 1) a += __shfl_down_sync(0xffffffffu, a, o);
        if (lane == 0) pns[w] = rsqrtf(a);
    }
}

__global__ void fill_csr(const int* __restrict__ ei, int E, int* curi, int* curo,
                         int* __restrict__ cii, int* __restrict__ cio) {
    int i = blockIdx.x * blockDim.x + threadIdx.x;
    if (i >= E) return;
    int s = ei[i], d = ei[E + i];
    int po = atomicAdd(curo + s, 1);
    cio[po] = d;
    int pi = atomicAdd(curi + d, 1);
    cii[pi] = s;
}

__global__ void splitW_all(const float* __restrict__ w_d0, const float* __restrict__ w_d,
                           const float* __restrict__ w_u, bf16* __restrict__ hi,
                           bf16* __restrict__ lo) {
    int idx = blockIdx.x * blockDim.x + threadIdx.x;
    float v;
    int o;
    if (idx < 32768) {
        int k = idx >> 8, c = idx & 255;
        v = w_d0[idx];
        o = c * 128 + k;
    } else {
        int t = idx - 32768;
        if (t >= 6 * 65536) return;
        int mat = t >> 16, e = t & 65535;
        int k = e >> 8, c = e & 255;
        v = (mat < 3) ? w_d[mat * 65536 + e] : w_u[(mat - 3) * 65536 + e];
        o = (1 + mat) * 65536 + c * 256 + k;
    }
    bf16 h = __float2bfloat16(v);
    hi[o] = h;
    lo[o] = __float2bfloat16(v - __bfloat162float(h));
}

// sparse GCN + optional fused score (p != nullptr) -> writes full dot
__global__ void spmv_gcn(const int* __restrict__ rp, const int* __restrict__ ci,
                         const float* __restrict__ z, const float* __restrict__ dinv,
                         const float* __restrict__ fil, const float* __restrict__ bias,
                         float* __restrict__ Y, int relu,
                         const float* __restrict__ p, float* __restrict__ scout) {
    int c = blockIdx.x * 8 + (threadIdx.x >> 5);
    int lane = threadIdx.x & 31;
    float acc[8] = {0.f, 0.f, 0.f, 0.f, 0.f, 0.f, 0.f, 0.f};
    int e0 = rp[c], e1 = rp[c + 1];
    for (int e = e0; e < e1; e++) {
        int r = ci[e];
        const float4* zp = (const float4*)(z + (size_t)r * CH + lane * 8);
        float4 a = zp[0], b = zp[1];
        acc[0] += a.x; acc[1] += a.y; acc[2] += a.z; acc[3] += a.w;
        acc[4] += b.x; acc[5] += b.y; acc[6] += b.z; acc[7] += b.w;
    }
    const float4* zc = (const float4*)(z + (size_t)c * CH + lane * 8);
    float4 za = zc[0], zb = zc[1];
    float zv[8] = {za.x, za.y, za.z, za.w, zb.x, zb.y, zb.z, zb.w};
    float f = fil[c], dv = dinv[c];
    float* yo = Y + (size_t)c * CH + lane * 8;
    float dot = 0.f;
#pragma unroll
    for (int q = 0; q < 8; q++) {
        float v = dv * (acc[q] + f * zv[q]) + bias[lane * 8 + q];
        if (relu) v = fmaxf(v, 0.f);
        yo[q] = v;
        if (p) dot += v * p[lane * 8 + q];
    }
    if (p) {
#pragma unroll
        for (int o = 16; o; o >>= 1) dot += __shfl_down_sync(0xffffffffu, dot, o);
        if (lane == 0) scout[c] = dot;
    }
}

// sparse (A+I)^2 restricted to kept rows/cols (global atomics; A1f pre-zeroed)
__global__ void sparse_augment(const int* __restrict__ pm, const int* __restrict__ colmap,
                               const int* __restrict__ rp, const int* __restrict__ ci,
                               float* __restrict__ A1f, int k) {
    int i = blockIdx.x;
    int pi = pm[i];
    int warp = threadIdx.x >> 5, lane = threadIdx.x & 31;
    float* row = A1f + (size_t)i * k;
    int b0 = rp[pi], b1 = rp[pi + 1];
    for (int e = b0 + threadIdx.x; e < b1; e += 256) {
        int j = colmap[ci[e]];
        if (j >= 0) atomicAdd(row + j, 2.f);
    }
    for (int e1 = b0 + warp; e1 < b1; e1 += 8) {
        int c = ci[e1];
        int c0 = rp[c], c1 = rp[c + 1];
        for (int e2 = c0 + lane; e2 < c1; e2 += 32) {
            int j = colmap[ci[e2]];
            if (j >= 0) atomicAdd(row + j, 1.f);
        }
    }
}

__global__ void finalize_A1(const float* __restrict__ Af, bf16* __restrict__ A,
                            bf16* __restrict__ AT, float* __restrict__ deg, int k) {
    __shared__ float t[64][65];
    int bx = blockIdx.x * 64, by = blockIdx.y * 64;
    int tid = threadIdx.x;
#pragma unroll
    for (int q = 0; q < 16; q++) {
        int s = q * 256 + tid;
        int r = s >> 6, c = s & 63;
        float v = Af[(size_t)(by + r) * k + bx + c];
        if (by + r == bx + c) v = 0.f;
        A[(size_t)(by + r) * k + bx + c] = __float2bfloat16(v);
        t[r][c] = v;
    }
    __syncthreads();
#pragma unroll
    for (int q = 0; q < 16; q++) {
        int s = q * 256 + tid;
        int r = s >> 6, c = s & 63;
        AT[(size_t)(bx + r) * k + by + c] = __float2bfloat16(t[c][r]);
    }
    if (tid < 64) {
        float s = 0.f;
#pragma unroll
        for (int r = 0; r < 64; r++) s += t[r][tid];
        atomicAdd(deg + bx + tid, s);
    }
}

// sum 4 split-K slices + 2*Aprev[pm[r],pm[c]], zero diag, colsum, emit A + AT
__global__ void finalize_aug(const float* __restrict__ Af, const bf16* __restrict__ Aprev,
                             const int* __restrict__ pm, int k, int nprev,
                             bf16* __restrict__ A, bf16* __restrict__ AT,
                             float* __restrict__ deg) {
    __shared__ float t[64][65];
    __shared__ int pmc[64], pmr[64];
    int bx = blockIdx.x * 64, by = blockIdx.y * 64;
    int tid = threadIdx.x;
    if (tid < 64) pmc[tid] = pm[bx + tid];
    else if (tid < 128) pmr[tid - 64] = pm[by + tid - 64];
    __syncthreads();
    size_t kk = (size_t)k * k;
#pragma unroll
    for (int q = 0; q < 16; q++) {
        int s = q * 256 + tid;
        int r = s >> 6, c = s & 63;
        size_t off = (size_t)(by + r) * k + bx + c;
        float v = Af[off] + Af[kk + off] + Af[2 * kk + off] + Af[3 * kk + off] +
                  2.f * __bfloat162float(Aprev[(size_t)pmr[r] * nprev + pmc[c]]);
        if (by + r == bx + c) v = 0.f;
        A[off] = __float2bfloat16(v);
        t[r][c] = v;
    }
    __syncthreads();
#pragma unroll
    for (int q = 0; q < 16; q++) {
        int s = q * 256 + tid;
        int r = s >> 6, c = s & 63;
        AT[(size_t)(bx + r) * k + by + c] = __float2bfloat16(t[c][r]);
    }
    if (tid < 64) {
        float s = 0.f;
#pragma unroll
        for (int r = 0; r < 64; r++) s += t[r][tid];
        atomicAdd(deg + bx + tid, s);
    }
}

// ---------------- single-block radix top-k select ----------------
template <int SZ>
__global__ void topk_select(const float* __restrict__ s0, int k,
                            int* __restrict__ perm, int* __restrict__ colmap) {
    constexpr int PT = SZ / 1024;
    __shared__ uint32_t key[SZ];
    __shared__ int red[32];
    __shared__ int loc[1024];
    int tid = threadIdx.x;
#pragma unroll
    for (int q = 0; q < PT; q++) {
        int t = tid * PT + q;
        uint32_t b = __float_as_uint(s0[t]);
        key[t] = (b & 0x80000000u) ? ~b : (b | 0x80000000u);
    }
    __syncthreads();

    auto blk_count = [&](uint32_t cand, int strict) -> int {
        int cnt = 0;
#pragma unroll
        for (int q = 0; q < PT; q++) {
            uint32_t kv = key[tid * PT + q];
            cnt += strict ? (kv > cand) : (kv >= cand);
        }
#pragma unroll
        for (int o = 16; o; o >>= 1) cnt += __shfl_down_sync(0xffffffffu, cnt, o);
        if ((tid & 31) == 0) red[tid >> 5] = cnt;
        __syncthreads();
        if (tid < 32) {
            int a = red[tid];
#pragma unroll
            for (int o = 16; o; o >>= 1) a += __shfl_down_sync(0xffffffffu, a, o);
            if (tid == 0) red[0] = a;
        }
        __syncthreads();
        int r = red[0];
        __syncthreads();
        return r;
    };

    uint32_t theta = 0;
    for (int bit = 31; bit >= 0; bit--) {
        uint32_t cand = theta | (1u << bit);
        if (blk_count(cand, 0) >= k) theta = cand;
    }
    int count_gt = blk_count(theta, 1);
    int need_eq = k - count_gt;

    int sloc = 0;
#pragma unroll
    for (int q = 0; q < PT; q++) {
        uint32_t kv = key[tid * PT + q];
        sloc += (kv > theta) ? 1 : ((kv == theta) ? 65536 : 0);
    }
    loc[tid] = sloc;
    __syncthreads();
    for (int o = 1; o < 1024; o <<= 1) {
        int x = (tid >= o) ? loc[tid - o] : 0;
        __syncthreads();
        loc[tid] += x;
        __syncthreads();
    }
    int pref = loc[tid] - sloc;
    int gtp = pref & 0xffff, eqp = pref >> 16;
#pragma unroll
    for (int q = 0; q < PT; q++) {
        int i = tid * PT + q;
        uint32_t kv = key[i];
        bool gt = kv > theta;
        bool eq = (kv == theta);
        bool sel = gt || (eq && eqp < need_eq);
        if (sel) {
            int pos = gtp + (eqp < need_eq ? eqp : need_eq);
            perm[pos] = i;
            colmap[i] = pos;
        }
        gtp += gt;
        eqp += eq;
    }
}

__global__ void mean_part(const float* __restrict__ x, float* __restrict__ part) {
    int b = blockIdx.x, j = threadIdx.x;
    float s = 0.f;
    for (int r = b * 128; r < b * 128 + 128; r++) s += x[(size_t)r * CH + j];
    part[b * 256 + j] = s;
}

__global__ void mean_final(const float* __restrict__ part, float* __restrict__ out) {
    int j = threadIdx.x;
    float s = 0.f;
#pragma unroll
    for (int b = 0; b < 32; b++) s += part[b * 256 + j];
    out[j] = s / (float)N0;
}

// GCN final reduce over split-K partials + optional fused FULL score.
__global__ void reduce_gcn(const float* __restrict__ part, int S, int partStride, int M,
                           const bf16* __restrict__ zh, const bf16* __restrict__ zl,
                           const float* __restrict__ deg,
                           const float* __restrict__ bias, float* __restrict__ Y, int relu,
                           const float* __restrict__ p, float* __restrict__ scout) {
    int m = blockIdx.x, c = threadIdx.x;
    size_t idx = (size_t)m * 256 + c;
    float s = 0.f;
    for (int q = 0; q < S; q++) s += part[(size_t)q * partStride + idx];
    float z = __bfloat162float(zh[(size_t)c * M + m]) + __bfloat162float(zl[(size_t)c * M + m]);
    float dv = rsqrtf(deg[m] + 2.f);
    float v = dv * (s + 2.f * z) + bias[c];
    if (relu) v = fmaxf(v, 0.f);
    Y[idx] = v;
    if (p) {
        __shared__ float red[8];
        float d = v * p[c];
#pragma unroll
        for (int o = 16; o; o >>= 1) d += __shfl_down_sync(0xffffffffu, d, o);
        if ((c & 31) == 0) red[c >> 5] = d;
        __syncthreads();
        if (c < 8) {
            float a = red[c];
#pragma unroll
            for (int o = 4; o; o >>= 1) a += __shfl_down_sync(0xffu, a, o);
            if (c == 0) scout[m] = a;
        }
    }
}

// ---------------- shared tile loader (bf16, cp.async) ----------------
template <int G>
__device__ __forceinline__ void ld_tile(const bf16* __restrict__ src, int ld,
                                        int row0, int k0, uint16_t* dst, int tid,
                                        const int* __restrict__ pm) {
#pragma unroll
    for (int i = 0; i < 2; i++) {
        int s = tid + i * 256;
        int r = s >> 2, c8 = (s & 3) * 8;
        int row = row0 + r;
        if (G) row = pm[row];
        const bf16* g = src + (size_t)row * ld + k0 + c8;
        uint32_t sm = (uint32_t)__cvta_generic_to_shared(dst + r * 40 + c8);
        asm volatile("cp.async.ca.shared.global [%0], [%1], 16;\n" ::"r"(sm), "l"(g));
    }
}

// ---------------- MMA compute helper ----------------
__device__ __forceinline__ void mma_block(const uint16_t* Asb, const uint16_t* Bsb,
                                          int ks, int g, int tg, int wm, int wn,
                                          float acc[4][4][4]) {
    uint32_t af[4][4], bfr[4][2];
    const int kc = ks + 2 * tg;
#pragma unroll
    for (int mf = 0; mf < 4; mf++) {
        int m = wm * 64 + mf * 16 + g;
        af[mf][0] = *(const uint32_t*)&Asb[m * 40 + kc];
        af[mf][1] = *(const uint32_t*)&Asb[(m + 8) * 40 + kc];
        af[mf][2] = *(const uint32_t*)&Asb[m * 40 + kc + 8];
        af[mf][3] = *(const uint32_t*)&Asb[(m + 8) * 40 + kc + 8];
    }
#pragma unroll
    for (int nf = 0; nf < 4; nf++) {
        int n = wn * 32 + nf * 8 + g;
        bfr[nf][0] = *(const uint32_t*)&Bsb[n * 40 + kc];
        bfr[nf][1] = *(const uint32_t*)&Bsb[n * 40 + kc + 8];
    }
#pragma unroll
    for (int mf = 0; mf < 4; mf++)
#pragma unroll
        for (int nf = 0; nf < 4; nf++)
            asm volatile(
                "mma.sync.aligned.m16n8k16.row.col.f32.bf16.bf16.f32 "
                "{%0,%1,%2,%3},{%4,%5,%6,%7},{%8,%9},{%0,%1,%2,%3};"
                : "+f"(acc[mf][nf][0]), "+f"(acc[mf][nf][1]),
                  "+f"(acc[mf][nf][2]), "+f"(acc[mf][nf][3])
                : "r"(af[mf][0]), "r"(af[mf][1]), "r"(af[mf][2]),
                  "r"(af[mf][3]), "r"(bfr[nf][0]), "r"(bfr[nf][1]));
}

// ---------------- bf16-operand GEMM (AᵀZ + augment), split-K partial stores ----------------
// RACE-FREE pipeline: next-stage cp.async issued only AFTER the barrier that
// proves all readers of that stage (previous compute) are done.
template <int NPROD, int G>
__global__ void __launch_bounds__(256, 2) mma_gemm(
    const bf16* __restrict__ A0p, int lda,
    const bf16* __restrict__ B0p, const bf16* __restrict__ B1p, int ldb,
    float* __restrict__ Cp, int ldc, int ksplit, size_t partStride,
    const int* __restrict__ pm) {
    constexpr int PB = (NPROD >= 2) ? 2 : 1;
    constexpr int TS = 128 * 40;
    extern __shared__ __align__(16) uint16_t sh[];

    const int tid = threadIdx.x;
    const int lane = tid & 31, warp = tid >> 5;
    const int g = lane >> 2, tg = lane & 3;
    const int wm = warp >> 2, wn = warp & 3;
    const int m0 = blockIdx.y * 128, j0 = blockIdx.x * 128;

    float acc[4][4][4];
#pragma unroll
    for (int a = 0; a < 4; a++)
#pragma unroll
        for (int b = 0; b < 4; b++)
#pragma unroll
            for (int e = 0; e < 4; e++) acc[a][b][e] = 0.f;

    auto load_stage = [&](int st, int k0) {
        ld_tile<G>(A0p, lda, m0, k0, sh + st * TS, tid, pm);
        ld_tile<G>(B0p, ldb, j0, k0, sh + (2 + st) * TS, tid, pm);
        if (PB == 2) ld_tile<G>(B1p, ldb, j0, k0, sh + (4 + st) * TS, tid, pm);
        asm volatile("cp.async.commit_group;\n" ::);
    };

    const int kb = blockIdx.z * ksplit;
    const int nt = ksplit / 32;

    load_stage(0, kb);
    for (int it = 0; it < nt; it++) {
        asm volatile("cp.async.wait_group 0;\n" ::);
        __syncthreads();  // stage it&1 visible to all; compute(it-1) readers done
        if (it + 1 < nt) load_stage((it + 1) & 1, kb + (it + 1) * 32);
        const int st = it & 1;
#pragma unroll
        for (int ks = 0; ks < 32; ks += 16)
            mma_block(sh + st * TS, sh + (2 + st) * TS, ks, g, tg, wm, wn, acc);
        if (PB == 2) {
#pragma unroll
            for (int ks = 0; ks < 32; ks += 16)
                mma_block(sh + st * TS, sh + (4 + st) * TS, ks, g, tg, wm, wn, acc);
        }
    }

#pragma unroll
    for (int mf = 0; mf < 4; mf++)
#pragma unroll
        for (int nf = 0; nf < 4; nf++)
#pragma unroll
            for (int e = 0; e < 4; e++) {
                int m = m0 + wm * 64 + mf * 16 + g + (e >> 1) * 8;
                int c = j0 + wn * 32 + nf * 8 + 2 * tg + (e & 1);
                Cp[(size_t)blockIdx.z * partStride + (size_t)m * ldc + c] = acc[mf][nf][e];
            }
}

// ---------------- fused XW GEMM (race-free pipeline, single A buffer) ----------------
// IN=1: A = Xsrc[m][k]
// IN=2: A = Xsrc[idx[m]][k] * tanh(s[idx[m]]*pn)
// IN=3: A = Xsrc[m][k] + (idx[m]>=0 ? xcur[idx[m]][k] : 0)
// MODE=1: z = rsqrt(scl[m]+2)*acc -> zhi/zlo transposed [c*n+m]
// MODE=2: z = scl[m]*acc -> fp32 [m*256+c]
template <int MODE, int IN>
__global__ void __launch_bounds__(256, 2) xw_gemm(
    const float* __restrict__ Xsrc, int K,
    const float* __restrict__ xcur, const int* __restrict__ idx,
    const float* __restrict__ s, const float* __restrict__ pn,
    const bf16* __restrict__ Bh, const bf16* __restrict__ Bl,
    void* __restrict__ Cp, void* __restrict__ C2p, int n,
    const float* __restrict__ scl) {
    extern __shared__ __align__(16) uint16_t sh[];
    uint16_t* Ahi = sh;
    uint16_t* Alo = sh + 5120;
    uint16_t* Bst = sh + 2 * 5120;

    const int tid = threadIdx.x;
    const int lane = tid & 31, warp = tid >> 5;
    const int g = lane >> 2, tg = lane & 3;
    const int wm = warp >> 2, wn = warp & 3;
    const int m0 = blockIdx.y * 128, j0 = blockIdx.x * 128;

    float acc[4][4][4];
#pragma unroll
    for (int a = 0; a < 4; a++)
#pragma unroll
        for (int b = 0; b < 4; b++)
#pragma unroll
            for (int e = 0; e < 4; e++) acc[a][b][e] = 0.f;

    auto loadB = [&](int st, int k0) {
        ld_tile<0>(Bh, K, j0, k0, Bst + st * 2 * 5120, tid, nullptr);
        ld_tile<0>(Bl, K, j0, k0, Bst + (st * 2 + 1) * 5120, tid, nullptr);
        asm volatile("cp.async.commit_group;\n" ::);
    };

    const int arow = tid >> 1;
    const int coff = (tid & 1) * 16;
    const int m = m0 + arow;
    int srow = 0;
    float gate = 1.f;
    if (IN == 2) {
        srow = idx[m];
        gate = tanhf(s[srow] * pn[0]);
    } else if (IN == 3) {
        srow = idx[m];
    }

    const int nt = K / 32;
    loadB(0, 0);
    for (int it = 0; it < nt; it++) {
        // fp32 A loads into regs (independent of shared state)
        float av[16];
        int kb = it * 32 + coff;
        if (IN == 1) {
#pragma unroll
            for (int q = 0; q < 4; q++) {
                float4 v = *(const float4*)(Xsrc + (size_t)m * K + kb + q * 4);
                av[q * 4] = v.x; av[q * 4 + 1] = v.y; av[q * 4 + 2] = v.z; av[q * 4 + 3] = v.w;
            }
        } else if (IN == 2) {
#pragma unroll
            for (int q = 0; q < 4; q++) {
                float4 v = *(const float4*)(Xsrc + (size_t)srow * K + kb + q * 4);
                av[q * 4] = v.x * gate; av[q * 4 + 1] = v.y * gate;
                av[q * 4 + 2] = v.z * gate; av[q * 4 + 3] = v.w * gate;
            }
        } else {
#pragma unroll
            for (int q = 0; q < 4; q++) {
                float4 v = *(const float4*)(Xsrc + (size_t)m * K + kb + q * 4);
                av[q * 4] = v.x; av[q * 4 + 1] = v.y; av[q * 4 + 2] = v.z; av[q * 4 + 3] = v.w;
            }
            if (srow >= 0) {
#pragma unroll
                for (int q = 0; q < 4; q++) {
                    float4 v = *(const float4*)(xcur + (size_t)srow * K + kb + q * 4);
                    av[q * 4] += v.x; av[q * 4 + 1] += v.y;
                    av[q * 4 + 2] += v.z; av[q * 4 + 3] += v.w;
                }
            }
        }
        asm volatile("cp.async.wait_group 0;\n" ::);
        __syncthreads();  // B stage it&1 visible; compute(it-1) readers done
        if (it + 1 < nt) loadB((it + 1) & 1, (it + 1) * 32);
#pragma unroll
        for (int e = 0; e < 16; e++) {
            float v = av[e];
            bf16 h = __float2bfloat16(v);
            Ahi[arow * 40 + coff + e] = __bfloat16_as_ushort(h);
            Alo[arow * 40 + coff + e] =
                __bfloat16_as_ushort(__float2bfloat16(v - __bfloat162float(h)));
        }
        __syncthreads();
        const uint16_t* Bhi_s = Bst + (it & 1) * 2 * 5120;
        const uint16_t* Blo_s = Bhi_s + 5120;
#pragma unroll
        for (int ks = 0; ks < 32; ks += 16) {
            mma_block(Ahi, Bhi_s, ks, g, tg, wm, wn, acc);
            mma_block(Ahi, Blo_s, ks, g, tg, wm, wn, acc);
            mma_block(Alo, Bhi_s, ks, g, tg, wm, wn, acc);
        }
    }

#pragma unroll
    for (int mf = 0; mf < 4; mf++)
#pragma unroll
        for (int nf = 0; nf < 4; nf++)
#pragma unroll
            for (int e = 0; e < 4; e++) {
                int mm = m0 + wm * 64 + mf * 16 + g + (e >> 1) * 8;
                int c = j0 + wn * 32 + nf * 8 + 2 * tg + (e & 1);
                float v = acc[mf][nf][e];
                if (MODE == 1) {
                    v *= rsqrtf(scl[mm] + 2.f);
                    bf16 h = __float2bfloat16(v);
                    ((bf16*)Cp)[(size_t)c * n + mm] = h;
                    ((bf16*)C2p)[(size_t)c * n + mm] =
                        __float2bfloat16(v - __bfloat162float(h));
                } else {
                    ((float*)Cp)[(size_t)mm * 256 + c] = v * scl[mm];
                }
            }
}

// ---------------- host orchestration ----------------
#define SYM(p, s)                     \
    do {                              \
        void* _t = nullptr;           \
        cudaGetSymbolAddress(&_t, s); \
        p = (decltype(p))_t;          \
    } while (0)

extern "C" void kernel_launch(void* const* d_in, const int* in_sizes, int n_in,
                              void* d_out, int out_size) {
    const float* x_in = (const float*)d_in[0];
    const int* ei     = (const int*)d_in[1];
    const float* w_d0 = (const float*)d_in[3];
    const float* b_d0 = (const float*)d_in[4];
    const float* w_d  = (const float*)d_in[5];
    const float* b_d  = (const float*)d_in[6];
    const float* p_at = (const float*)d_in[7];
    const float* w_u  = (const float*)d_in[8];
    const float* b_u  = (const float*)d_in[9];
    float* out = (float*)d_out;
    const int E = in_sizes[1] / 2;

    bf16 *A1, *A2, *A3, *AT1, *AT2, *AT3, *WH, *WL, *zhi, *zlo;
    float *X0, *X1, *X2, *Xc, *Cpart, *zf, *A1f, *dinv0, *fil0, *sc, *pns, *mpart;
    int *zblk, *perm, *colmap, *rpi, *rpo, *cii, *cio, *curi, *curo;
    SYM(A1, g_A1);   SYM(A2, g_A2);   SYM(A3, g_A3);
    SYM(AT1, g_AT1); SYM(AT2, g_AT2); SYM(AT3, g_AT3);
    SYM(WH, g_WH);   SYM(WL, g_WL);
    SYM(zhi, g_zhi); SYM(zlo, g_zlo);
    SYM(X0, g_X0);   SYM(X1, g_X1);   SYM(X2, g_X2);
    SYM(Xc, g_Xc);   SYM(Cpart, g_Cpart);
    SYM(zf, g_z);    SYM(A1f, g_A1f);
    SYM(zblk, g_zblk);
    SYM(dinv0, g_dinv0); SYM(fil0, g_fil0);
    SYM(sc, g_s);    SYM(pns, g_pns); SYM(mpart, g_mpart);
    SYM(perm, g_perm); SYM(colmap, g_colmap);
    SYM(rpi, g_rpi); SYM(rpo, g_rpo); SYM(cii, g_cii); SYM(cio, g_cio);
    SYM(curi, g_curi); SYM(curo, g_curo);
    int* cnt = zblk;
    float* deg = (float*)(zblk + 3 * N0);

    cudaFuncSetAttribute(mma_gemm<2, 0>, cudaFuncAttributeMaxDynamicSharedMemorySize, 61440);
    cudaFuncSetAttribute(mma_gemm<1, 1>, cudaFuncAttributeMaxDynamicSharedMemorySize, 40960);
    cudaFuncSetAttribute(xw_gemm<2, 1>, cudaFuncAttributeMaxDynamicSharedMemorySize, 61440);
    cudaFuncSetAttribute(xw_gemm<2, 3>, cudaFuncAttributeMaxDynamicSharedMemorySize, 61440);
    cudaFuncSetAttribute(xw_gemm<1, 2>, cudaFuncAttributeMaxDynamicSharedMemorySize, 61440);
    cudaFuncSetAttribute(xw_gemm<1, 3>, cudaFuncAttributeMaxDynamicSharedMemorySize, 61440);

    bf16* Alv[4] = {nullptr, A1, A2, A3};
    bf16* ATlv[4] = {nullptr, AT1, AT2, AT3};
    float* Xs[3] = {X0, X1, X2};
    const int ns[4] = {4096, 2048, 1024, 512};

    // ---- setup ----
    cudaMemsetAsync(zblk, 0, 7 * N0 * sizeof(int));
    cudaMemsetAsync(colmap, 0xFF, 3 * N0 * sizeof(int));
    splitW_all<<<cdiv(32768 + 6 * 65536, 256), 256>>>(w_d0, w_d, w_u, WH, WL);
    count_deg<<<cdiv(E, 256), 256>>>(ei, E, cnt);
    scan_build<<<1, 1024>>>(cnt, rpi, rpo, curi, curo, dinv0, fil0, p_at, pns);
    fill_csr<<<cdiv(E, 256), 256>>>(ei, E, curi, curo, cii, cio);

    // dense GCN levels 1..3 (full score fused into reduce when pnext)
    auto gcn = [&](int lvl, int slot, const float* Xsrc, const int* pidx, int IN,
                   const float* bias, float* Y, int relu, const float* pnext) {
        int n = ns[lvl];
        if (IN == 2)
            xw_gemm<1, 2><<<dim3(2, n / 128), 256, 61440>>>(
                Xsrc, 256, nullptr, pidx, sc, pns + (lvl - 1), WH + slot * 65536,
                WL + slot * 65536, zhi, zlo, n, deg + lvl * N0);
        else
            xw_gemm<1, 3><<<dim3(2, n / 128), 256, 61440>>>(
                Xsrc, 256, Xc, pidx, nullptr, nullptr, WH + slot * 65536,
                WL + slot * 65536, zhi, zlo, n, deg + lvl * N0);
        mma_gemm<2, 0><<<dim3(2, n / 128, 8), 256, 61440>>>(
            ATlv[lvl], n, zhi, zlo, n, Cpart, 256, n / 8, (size_t)n * 256, nullptr);
        reduce_gcn<<<n, 256>>>(Cpart, 8, n * 256, n, zhi, zlo, deg + lvl * N0,
                               bias, Y, relu, pnext, sc);
    };

    // ---- level-0 down GCN (score fused into spmv) ----
    xw_gemm<2, 1><<<dim3(2, N0 / 128), 256, 61440>>>(
        x_in, 128, nullptr, nullptr, nullptr, nullptr, WH, WL, zf, nullptr, N0, dinv0);
    spmv_gcn<<<N0 / 8, 256>>>(rpi, cii, zf, dinv0, fil0, b_d0, X0, 1, p_at, sc);

    // ---- down path ----
    for (int i = 0; i < 3; i++) {
        int n = ns[i], k = ns[i + 1];
        int* pm = perm + i * 2048;
        int* cm = colmap + i * N0;

        if (i == 0) topk_select<4096><<<1, 1024>>>(sc, k, pm, cm);
        else if (i == 1) topk_select<2048><<<1, 1024>>>(sc, k, pm, cm);
        else topk_select<1024><<<1, 1024>>>(sc, k, pm, cm);

        if (i == 0) {
            cudaMemsetAsync(A1f, 0, (size_t)k * k * sizeof(float));
            sparse_augment<<<k, 256>>>(pm, cm, rpo, cio, A1f, k);
            finalize_A1<<<dim3(k / 64, k / 64), 256>>>(A1f, A1, AT1, deg + N0, k);
        } else {
            mma_gemm<1, 1><<<dim3(k / 128, k / 128, 4), 256, 40960>>>(
                Alv[i], n, ATlv[i], nullptr, n, A1f, k, n / 4, (size_t)k * k, pm);
            finalize_aug<<<dim3(k / 64, k / 64), 256>>>(A1f, Alv[i], pm, k, n,
                                                        Alv[i + 1], ATlv[i + 1],
                                                        deg + (i + 1) * N0);
        }

        float* Y = (i < 2) ? Xs[i + 1] : Xc;
        const float* pnext = (i < 2) ? (p_at + (i + 1) * CH) : nullptr;
        gcn(i + 1, 1 + i, Xs[i], pm, 2, b_d + i * CH, Y, 1, pnext);
    }

    // ---- up path ----
    for (int i = 0; i < 3; i++) {
        int j = 2 - i;
        if (j == 0) {
            xw_gemm<2, 3><<<dim3(2, N0 / 128), 256, 61440>>>(
                X0, 256, Xc, colmap, nullptr, nullptr,
                WH + (4 + i) * 65536, WL + (4 + i) * 65536, zf, nullptr, N0, dinv0);
            spmv_gcn<<<N0 / 8, 256>>>(rpi, cii, zf, dinv0, fil0, b_u + i * CH, Xc, 0,
                                      nullptr, nullptr);
        } else {
            gcn(j, 4 + i, Xs[j], colmap + j * N0, 3, b_u + i * CH, Xc, 1, nullptr);
        }
    }

    mean_part<<<32, 256>>>(Xc, mpart);
    mean_final<<<1, 256>>>(mpart, out);
}

// round 14
// speedup vs baseline: 1.0140x; 1.0140x over previous
#include <cuda_runtime.h>
#include <cuda_bf16.h>
#include <math.h>
#include <stdint.h>

#define N0 4096
#define CH 256
#define EMAX 131072

using bf16 = __nv_bfloat16;

// ---------------- scratch ----------------
__device__ bf16  g_A1[2048 * 2048];
__device__ bf16  g_A2[1024 * 1024];
__device__ bf16  g_A3[512 * 512];
__device__ bf16  g_AT1[2048 * 2048];
__device__ bf16  g_AT2[1024 * 1024];
__device__ bf16  g_AT3[512 * 512];
__device__ float g_A1f[2048 * 2048];   // augment split-K slices
__device__ float g_X0[N0 * CH];
__device__ float g_X1[2048 * CH];
__device__ float g_X2[1024 * CH];
__device__ float g_Xc[N0 * CH];
__device__ float g_z[N0 * CH];
__device__ bf16  g_WH[7 * 65536];
__device__ bf16  g_WL[7 * 65536];
__device__ bf16  g_zhi[CH * N0];
__device__ bf16  g_zlo[CH * N0];
__device__ float g_Cpart[8 * 2048 * CH];
__device__ int   g_zblk[7 * N0];       // [cnt: 3*N0 | deg: 4*N0(as float)]
__device__ float g_dinv0[N0];
__device__ float g_fil0[N0];
__device__ float g_s[N0];
__device__ float g_pns[3];
__device__ int   g_perm[3][2048];
__device__ int   g_colmap[3][N0];
__device__ int g_rpi[N0 + 1], g_rpo[N0 + 1];
__device__ int g_cii[EMAX], g_cio[EMAX];
__device__ int g_curi[N0], g_curo[N0];
__device__ float g_mpart[32 * 256];

static inline int cdiv(int a, int b) { return (a + b - 1) / b; }

// ---------------- CSR build ----------------
__global__ void count_deg(const int* __restrict__ ei, int E, int* __restrict__ cnt) {
    int i = blockIdx.x * blockDim.x + threadIdx.x;
    if (i >= E) return;
    int s = ei[i], d = ei[E + i];
    atomicAdd(cnt + N0 + s, 1);
    atomicAdd(cnt + d, 1);
    if (s == d) atomicAdd(cnt + 2 * N0 + s, 1);
}

__device__ void scan4096(const int* __restrict__ cnt, int* __restrict__ rp,
                         int* __restrict__ cur, int* loc) {
    int t = threadIdx.x;
    int base = t * 4;
    int v0 = cnt[base], v1 = cnt[base + 1], v2 = cnt[base + 2], v3 = cnt[base + 3];
    int s01 = v0 + v1;
    int s = s01 + v2 + v3;
    loc[t] = s;
    __syncthreads();
    for (int o = 1; o < 1024; o <<= 1) {
        int x = (t >= o) ? loc[t - o] : 0;
        __syncthreads();
        loc[t] += x;
        __syncthreads();
    }
    int excl = loc[t] - s;
    rp[base] = excl;           cur[base] = excl;
    rp[base + 1] = excl + v0;  cur[base + 1] = excl + v0;
    rp[base + 2] = excl + s01; cur[base + 2] = excl + s01;
    rp[base + 3] = excl + s01 + v2; cur[base + 3] = excl + s01 + v2;
    if (t == 1023) rp[4096] = excl + s;
}

__global__ void scan_build(const int* __restrict__ cnt,
                           int* rpi, int* rpo, int* curi, int* curo,
                           float* __restrict__ dinv, float* __restrict__ fil,
                           const float* __restrict__ p_at, float* __restrict__ pns) {
    __shared__ int loc[1024];
    scan4096(cnt, rpi, curi, loc);
    __syncthreads();
    scan4096(cnt + N0, rpo, curo, loc);
    int t = threadIdx.x;
#pragma unroll
    for (int q = 0; q < 4; q++) {
        int c = t * 4 + q;
        float f = (cnt[2 * N0 + c] == 0) ? 2.f : 0.f;
        fil[c] = f;
        dinv[c] = rsqrtf((float)cnt[c] + f);
    }
    if (t < 96) {
        int w = t >> 5, lane = t & 31;
        float a = 0.f;
#pragma unroll
        for (int q = 0; q < 8; q++) {
            float v = p_at[w * 256 + lane + 32 * q];
            a += v * v;
        }
#pragma unroll
        for (int o = 16; o; o >>= 1) a += __shfl_down_sync(0xffffffffu, a, o);
        if (lane == 0) pns[w] = rsqrtf(a);
    }
}

__global__ void fill_csr(const int* __restrict__ ei, int E, int* curi, int* curo,
                         int* __restrict__ cii, int* __restrict__ cio) {
    int i = blockIdx.x * blockDim.x + threadIdx.x;
    if (i >= E) return;
    int s = ei[i], d = ei[E + i];
    int po = atomicAdd(curo + s, 1);
    cio[po] = d;
    int pi = atomicAdd(curi + d, 1);
    cii[pi] = s;
}

__global__ void splitW_all(const float* __restrict__ w_d0, const float* __restrict__ w_d,
                           const float* __restrict__ w_u, bf16* __restrict__ hi,
                           bf16* __restrict__ lo) {
    int idx = blockIdx.x * blockDim.x + threadIdx.x;
    float v;
    int o;
    if (idx < 32768) {
        int k = idx >> 8, c = idx & 255;
        v = w_d0[idx];
        o = c * 128 + k;
    } else {
        int t = idx - 32768;
        if (t >= 6 * 65536) return;
        int mat = t >> 16, e = t & 65535;
        int k = e >> 8, c = e & 255;
        v = (mat < 3) ? w_d[mat * 65536 + e] : w_u[(mat - 3) * 65536 + e];
        o = (1 + mat) * 65536 + c * 256 + k;
    }
    bf16 h = __float2bfloat16(v);
    hi[o] = h;
    lo[o] = __float2bfloat16(v - __bfloat162float(h));
}

// sparse GCN + optional fused score (p != nullptr) -> writes full dot
__global__ void spmv_gcn(const int* __restrict__ rp, const int* __restrict__ ci,
                         const float* __restrict__ z, const float* __restrict__ dinv,
                         const float* __restrict__ fil, const float* __restrict__ bias,
                         float* __restrict__ Y, int relu,
                         const float* __restrict__ p, float* __restrict__ scout) {
    int c = blockIdx.x * 8 + (threadIdx.x >> 5);
    int lane = threadIdx.x & 31;
    float acc[8] = {0.f, 0.f, 0.f, 0.f, 0.f, 0.f, 0.f, 0.f};
    int e0 = rp[c], e1 = rp[c + 1];
    for (int e = e0; e < e1; e++) {
        int r = ci[e];
        const float4* zp = (const float4*)(z + (size_t)r * CH + lane * 8);
        float4 a = zp[0], b = zp[1];
        acc[0] += a.x; acc[1] += a.y; acc[2] += a.z; acc[3] += a.w;
        acc[4] += b.x; acc[5] += b.y; acc[6] += b.z; acc[7] += b.w;
    }
    const float4* zc = (const float4*)(z + (size_t)c * CH + lane * 8);
    float4 za = zc[0], zb = zc[1];
    float zv[8] = {za.x, za.y, za.z, za.w, zb.x, zb.y, zb.z, zb.w};
    float f = fil[c], dv = dinv[c];
    float* yo = Y + (size_t)c * CH + lane * 8;
    float dot = 0.f;
#pragma unroll
    for (int q = 0; q < 8; q++) {
        float v = dv * (acc[q] + f * zv[q]) + bias[lane * 8 + q];
        if (relu) v = fmaxf(v, 0.f);
        yo[q] = v;
        if (p) dot += v * p[lane * 8 + q];
    }
    if (p) {
#pragma unroll
        for (int o = 16; o; o >>= 1) dot += __shfl_down_sync(0xffffffffu, dot, o);
        if (lane == 0) scout[c] = dot;
    }
}

// sparse (A+I)^2 restricted to kept rows/cols (global atomics; A1f pre-zeroed)
__global__ void sparse_augment(const int* __restrict__ pm, const int* __restrict__ colmap,
                               const int* __restrict__ rp, const int* __restrict__ ci,
                               float* __restrict__ A1f, int k) {
    int i = blockIdx.x;
    int pi = pm[i];
    int warp = threadIdx.x >> 5, lane = threadIdx.x & 31;
    float* row = A1f + (size_t)i * k;
    int b0 = rp[pi], b1 = rp[pi + 1];
    for (int e = b0 + threadIdx.x; e < b1; e += 256) {
        int j = colmap[ci[e]];
        if (j >= 0) atomicAdd(row + j, 2.f);
    }
    for (int e1 = b0 + warp; e1 < b1; e1 += 8) {
        int c = ci[e1];
        int c0 = rp[c], c1 = rp[c + 1];
        for (int e2 = c0 + lane; e2 < c1; e2 += 32) {
            int j = colmap[ci[e2]];
            if (j >= 0) atomicAdd(row + j, 1.f);
        }
    }
}

__global__ void finalize_A1(const float* __restrict__ Af, bf16* __restrict__ A,
                            bf16* __restrict__ AT, float* __restrict__ deg, int k) {
    __shared__ float t[64][65];
    int bx = blockIdx.x * 64, by = blockIdx.y * 64;
    int tid = threadIdx.x;
#pragma unroll
    for (int q = 0; q < 16; q++) {
        int s = q * 256 + tid;
        int r = s >> 6, c = s & 63;
        float v = Af[(size_t)(by + r) * k + bx + c];
        if (by + r == bx + c) v = 0.f;
        A[(size_t)(by + r) * k + bx + c] = __float2bfloat16(v);
        t[r][c] = v;
    }
    __syncthreads();
#pragma unroll
    for (int q = 0; q < 16; q++) {
        int s = q * 256 + tid;
        int r = s >> 6, c = s & 63;
        AT[(size_t)(bx + r) * k + by + c] = __float2bfloat16(t[c][r]);
    }
    if (tid < 64) {
        float s = 0.f;
#pragma unroll
        for (int r = 0; r < 64; r++) s += t[r][tid];
        atomicAdd(deg + bx + tid, s);
    }
}

// sum 4 split-K slices + 2*Aprev[pm[r],pm[c]], zero diag, colsum, emit A + AT
__global__ void finalize_aug(const float* __restrict__ Af, const bf16* __restrict__ Aprev,
                             const int* __restrict__ pm, int k, int nprev,
                             bf16* __restrict__ A, bf16* __restrict__ AT,
                             float* __restrict__ deg) {
    __shared__ float t[64][65];
    __shared__ int pmc[64], pmr[64];
    int bx = blockIdx.x * 64, by = blockIdx.y * 64;
    int tid = threadIdx.x;
    if (tid < 64) pmc[tid] = pm[bx + tid];
    else if (tid < 128) pmr[tid - 64] = pm[by + tid - 64];
    __syncthreads();
    size_t kk = (size_t)k * k;
#pragma unroll
    for (int q = 0; q < 16; q++) {
        int s = q * 256 + tid;
        int r = s >> 6, c = s & 63;
        size_t off = (size_t)(by + r) * k + bx + c;
        float v = Af[off] + Af[kk + off] + Af[2 * kk + off] + Af[3 * kk + off] +
                  2.f * __bfloat162float(Aprev[(size_t)pmr[r] * nprev + pmc[c]]);
        if (by + r == bx + c) v = 0.f;
        A[off] = __float2bfloat16(v);
        t[r][c] = v;
    }
    __syncthreads();
#pragma unroll
    for (int q = 0; q < 16; q++) {
        int s = q * 256 + tid;
        int r = s >> 6, c = s & 63;
        AT[(size_t)(bx + r) * k + by + c] = __float2bfloat16(t[c][r]);
    }
    if (tid < 64) {
        float s = 0.f;
#pragma unroll
        for (int r = 0; r < 64; r++) s += t[r][tid];
        atomicAdd(deg + bx + tid, s);
    }
}

// ---------------- single-block radix top-k select ----------------
template <int SZ>
__global__ void topk_select(const float* __restrict__ s0, int k,
                            int* __restrict__ perm, int* __restrict__ colmap) {
    constexpr int PT = SZ / 1024;
    __shared__ uint32_t key[SZ];
    __shared__ int red[32];
    __shared__ int loc[1024];
    int tid = threadIdx.x;
#pragma unroll
    for (int q = 0; q < PT; q++) {
        int t = tid * PT + q;
        uint32_t b = __float_as_uint(s0[t]);
        key[t] = (b & 0x80000000u) ? ~b : (b | 0x80000000u);
    }
    __syncthreads();

    auto blk_count = [&](uint32_t cand, int strict) -> int {
        int cnt = 0;
#pragma unroll
        for (int q = 0; q < PT; q++) {
            uint32_t kv = key[tid * PT + q];
            cnt += strict ? (kv > cand) : (kv >= cand);
        }
#pragma unroll
        for (int o = 16; o; o >>= 1) cnt += __shfl_down_sync(0xffffffffu, cnt, o);
        if ((tid & 31) == 0) red[tid >> 5] = cnt;
        __syncthreads();
        if (tid < 32) {
            int a = red[tid];
#pragma unroll
            for (int o = 16; o; o >>= 1) a += __shfl_down_sync(0xffffffffu, a, o);
            if (tid == 0) red[0] = a;
        }
        __syncthreads();
        int r = red[0];
        __syncthreads();
        return r;
    };

    uint32_t theta = 0;
    for (int bit = 31; bit >= 0; bit--) {
        uint32_t cand = theta | (1u << bit);
        if (blk_count(cand, 0) >= k) theta = cand;
    }
    int count_gt = blk_count(theta, 1);
    int need_eq = k - count_gt;

    int sloc = 0;
#pragma unroll
    for (int q = 0; q < PT; q++) {
        uint32_t kv = key[tid * PT + q];
        sloc += (kv > theta) ? 1 : ((kv == theta) ? 65536 : 0);
    }
    loc[tid] = sloc;
    __syncthreads();
    for (int o = 1; o < 1024; o <<= 1) {
        int x = (tid >= o) ? loc[tid - o] : 0;
        __syncthreads();
        loc[tid] += x;
        __syncthreads();
    }
    int pref = loc[tid] - sloc;
    int gtp = pref & 0xffff, eqp = pref >> 16;
#pragma unroll
    for (int q = 0; q < PT; q++) {
        int i = tid * PT + q;
        uint32_t kv = key[i];
        bool gt = kv > theta;
        bool eq = (kv == theta);
        bool sel = gt || (eq && eqp < need_eq);
        if (sel) {
            int pos = gtp + (eqp < need_eq ? eqp : need_eq);
            perm[pos] = i;
            colmap[i] = pos;
        }
        gtp += gt;
        eqp += eq;
    }
}

__global__ void mean_part(const float* __restrict__ x, float* __restrict__ part) {
    int b = blockIdx.x, j = threadIdx.x;
    float s = 0.f;
    for (int r = b * 128; r < b * 128 + 128; r++) s += x[(size_t)r * CH + j];
    part[b * 256 + j] = s;
}

__global__ void mean_final(const float* __restrict__ part, float* __restrict__ out) {
    int j = threadIdx.x;
    float s = 0.f;
#pragma unroll
    for (int b = 0; b < 32; b++) s += part[b * 256 + j];
    out[j] = s / (float)N0;
}

// GCN final reduce over split-K partials + optional fused FULL score.
__global__ void reduce_gcn(const float* __restrict__ part, int S, int partStride, int M,
                           const bf16* __restrict__ zh, const bf16* __restrict__ zl,
                           const float* __restrict__ deg,
                           const float* __restrict__ bias, float* __restrict__ Y, int relu,
                           const float* __restrict__ p, float* __restrict__ scout) {
    int m = blockIdx.x, c = threadIdx.x;
    size_t idx = (size_t)m * 256 + c;
    float s = 0.f;
    for (int q = 0; q < S; q++) s += part[(size_t)q * partStride + idx];
    float z = __bfloat162float(zh[(size_t)c * M + m]) + __bfloat162float(zl[(size_t)c * M + m]);
    float dv = rsqrtf(deg[m] + 2.f);
    float v = dv * (s + 2.f * z) + bias[c];
    if (relu) v = fmaxf(v, 0.f);
    Y[idx] = v;
    if (p) {
        __shared__ float red[8];
        float d = v * p[c];
#pragma unroll
        for (int o = 16; o; o >>= 1) d += __shfl_down_sync(0xffffffffu, d, o);
        if ((c & 31) == 0) red[c >> 5] = d;
        __syncthreads();
        if (c < 8) {
            float a = red[c];
#pragma unroll
            for (int o = 4; o; o >>= 1) a += __shfl_down_sync(0xffu, a, o);
            if (c == 0) scout[m] = a;
        }
    }
}

// ---------------- shared tile loader (bf16, cp.async) ----------------
template <int G>
__device__ __forceinline__ void ld_tile(const bf16* __restrict__ src, int ld,
                                        int row0, int k0, uint16_t* dst, int tid,
                                        const int* __restrict__ pm) {
#pragma unroll
    for (int i = 0; i < 2; i++) {
        int s = tid + i * 256;
        int r = s >> 2, c8 = (s & 3) * 8;
        int row = row0 + r;
        if (G) row = pm[row];
        const bf16* g = src + (size_t)row * ld + k0 + c8;
        uint32_t sm = (uint32_t)__cvta_generic_to_shared(dst + r * 40 + c8);
        asm volatile("cp.async.ca.shared.global [%0], [%1], 16;\n" ::"r"(sm), "l"(g));
    }
}

// ---------------- MMA compute helper ----------------
__device__ __forceinline__ void mma_block(const uint16_t* Asb, const uint16_t* Bsb,
                                          int ks, int g, int tg, int wm, int wn,
                                          float acc[4][4][4]) {
    uint32_t af[4][4], bfr[4][2];
    const int kc = ks + 2 * tg;
#pragma unroll
    for (int mf = 0; mf < 4; mf++) {
        int m = wm * 64 + mf * 16 + g;
        af[mf][0] = *(const uint32_t*)&Asb[m * 40 + kc];
        af[mf][1] = *(const uint32_t*)&Asb[(m + 8) * 40 + kc];
        af[mf][2] = *(const uint32_t*)&Asb[m * 40 + kc + 8];
        af[mf][3] = *(const uint32_t*)&Asb[(m + 8) * 40 + kc + 8];
    }
#pragma unroll
    for (int nf = 0; nf < 4; nf++) {
        int n = wn * 32 + nf * 8 + g;
        bfr[nf][0] = *(const uint32_t*)&Bsb[n * 40 + kc];
        bfr[nf][1] = *(const uint32_t*)&Bsb[n * 40 + kc + 8];
    }
#pragma unroll
    for (int mf = 0; mf < 4; mf++)
#pragma unroll
        for (int nf = 0; nf < 4; nf++)
            asm volatile(
                "mma.sync.aligned.m16n8k16.row.col.f32.bf16.bf16.f32 "
                "{%0,%1,%2,%3},{%4,%5,%6,%7},{%8,%9},{%0,%1,%2,%3};"
                : "+f"(acc[mf][nf][0]), "+f"(acc[mf][nf][1]),
                  "+f"(acc[mf][nf][2]), "+f"(acc[mf][nf][3])
                : "r"(af[mf][0]), "r"(af[mf][1]), "r"(af[mf][2]),
                  "r"(af[mf][3]), "r"(bfr[nf][0]), "r"(bfr[nf][1]));
}

// ---------------- bf16-operand GEMM, 3-STAGE pipeline ----------------
// One barrier per K-iteration; prefetch of stage (it+2)%3 issued AFTER the
// barrier, whose target was last read by compute(it-1) -> provably race-free.
template <int NPROD, int G>
__global__ void __launch_bounds__(256, 2) mma_gemm(
    const bf16* __restrict__ A0p, int lda,
    const bf16* __restrict__ B0p, const bf16* __restrict__ B1p, int ldb,
    float* __restrict__ Cp, int ldc, int ksplit, size_t partStride,
    const int* __restrict__ pm) {
    constexpr int PB = (NPROD >= 2) ? 2 : 1;
    constexpr int TS = 128 * 40;            // u16 per tile
    constexpr int SS = (1 + PB) * TS;       // u16 per stage
    extern __shared__ __align__(16) uint16_t sh[];

    const int tid = threadIdx.x;
    const int lane = tid & 31, warp = tid >> 5;
    const int g = lane >> 2, tg = lane & 3;
    const int wm = warp >> 2, wn = warp & 3;
    const int m0 = blockIdx.y * 128, j0 = blockIdx.x * 128;

    float acc[4][4][4];
#pragma unroll
    for (int a = 0; a < 4; a++)
#pragma unroll
        for (int b = 0; b < 4; b++)
#pragma unroll
            for (int e = 0; e < 4; e++) acc[a][b][e] = 0.f;

    auto load_stage = [&](int st, int k0) {
        ld_tile<G>(A0p, lda, m0, k0, sh + st * SS, tid, pm);
        ld_tile<G>(B0p, ldb, j0, k0, sh + st * SS + TS, tid, pm);
        if (PB == 2) ld_tile<G>(B1p, ldb, j0, k0, sh + st * SS + 2 * TS, tid, pm);
        asm volatile("cp.async.commit_group;\n" ::);
    };

    const int kb = blockIdx.z * ksplit;
    const int nt = ksplit / 32;

    load_stage(0, kb);
    if (nt > 1) load_stage(1, kb + 32);
    int st = 0;
    for (int it = 0; it < nt; it++) {
        if (it + 1 < nt)
            asm volatile("cp.async.wait_group 1;\n" ::);
        else
            asm volatile("cp.async.wait_group 0;\n" ::);
        __syncthreads();  // stage st ready; compute(it-1) readers done
        if (it + 2 < nt) load_stage((st + 2) % 3, kb + (it + 2) * 32);
        const uint16_t* As = sh + st * SS;
        const uint16_t* Bs0 = As + TS;
#pragma unroll
        for (int ks = 0; ks < 32; ks += 16)
            mma_block(As, Bs0, ks, g, tg, wm, wn, acc);
        if (PB == 2) {
            const uint16_t* Bs1 = As + 2 * TS;
#pragma unroll
            for (int ks = 0; ks < 32; ks += 16)
                mma_block(As, Bs1, ks, g, tg, wm, wn, acc);
        }
        st = (st + 1) % 3;
    }

#pragma unroll
    for (int mf = 0; mf < 4; mf++)
#pragma unroll
        for (int nf = 0; nf < 4; nf++)
#pragma unroll
            for (int e = 0; e < 4; e++) {
                int m = m0 + wm * 64 + mf * 16 + g + (e >> 1) * 8;
                int c = j0 + wn * 32 + nf * 8 + 2 * tg + (e & 1);
                Cp[(size_t)blockIdx.z * partStride + (size_t)m * ldc + c] = acc[mf][nf][e];
            }
}

// ---------------- fused XW GEMM (round-8 proven pipeline) ----------------
// IN=1: A = Xsrc[m][k]
// IN=2: A = Xsrc[idx[m]][k] * tanh(s[idx[m]]*pn)
// IN=3: A = Xsrc[m][k] + (idx[m]>=0 ? xcur[idx[m]][k] : 0)
// MODE=1: z = rsqrt(scl[m]+2)*acc -> zhi/zlo transposed [c*n+m]
// MODE=2: z = scl[m]*acc -> fp32 [m*256+c]
template <int MODE, int IN>
__global__ void __launch_bounds__(256, 2) xw_gemm(
    const float* __restrict__ Xsrc, int K,
    const float* __restrict__ xcur, const int* __restrict__ idx,
    const float* __restrict__ s, const float* __restrict__ pn,
    const bf16* __restrict__ Bh, const bf16* __restrict__ Bl,
    void* __restrict__ Cp, void* __restrict__ C2p, int n,
    const float* __restrict__ scl) {
    extern __shared__ __align__(16) uint16_t sh[];
    uint16_t* Ahi = sh;
    uint16_t* Alo = sh + 5120;
    uint16_t* Bst = sh + 2 * 5120;

    const int tid = threadIdx.x;
    const int lane = tid & 31, warp = tid >> 5;
    const int g = lane >> 2, tg = lane & 3;
    const int wm = warp >> 2, wn = warp & 3;
    const int m0 = blockIdx.y * 128, j0 = blockIdx.x * 128;

    float acc[4][4][4];
#pragma unroll
    for (int a = 0; a < 4; a++)
#pragma unroll
        for (int b = 0; b < 4; b++)
#pragma unroll
            for (int e = 0; e < 4; e++) acc[a][b][e] = 0.f;

    auto loadB = [&](int st, int k0) {
        ld_tile<0>(Bh, K, j0, k0, Bst + st * 2 * 5120, tid, nullptr);
        ld_tile<0>(Bl, K, j0, k0, Bst + (st * 2 + 1) * 5120, tid, nullptr);
        asm volatile("cp.async.commit_group;\n" ::);
    };

    const int arow = tid >> 1;
    const int coff = (tid & 1) * 16;
    const int m = m0 + arow;
    int srow = 0;
    float gate = 1.f;
    if (IN == 2) {
        srow = idx[m];
        gate = tanhf(s[srow] * pn[0]);
    } else if (IN == 3) {
        srow = idx[m];
    }

    const int nt = K / 32;
    loadB(0, 0);
    for (int it = 0; it < nt; it++) {
        float av[16];
        int kb = it * 32 + coff;
        if (IN == 1) {
#pragma unroll
            for (int q = 0; q < 4; q++) {
                float4 v = *(const float4*)(Xsrc + (size_t)m * K + kb + q * 4);
                av[q * 4] = v.x; av[q * 4 + 1] = v.y; av[q * 4 + 2] = v.z; av[q * 4 + 3] = v.w;
            }
        } else if (IN == 2) {
#pragma unroll
            for (int q = 0; q < 4; q++) {
                float4 v = *(const float4*)(Xsrc + (size_t)srow * K + kb + q * 4);
                av[q * 4] = v.x * gate; av[q * 4 + 1] = v.y * gate;
                av[q * 4 + 2] = v.z * gate; av[q * 4 + 3] = v.w * gate;
            }
        } else {
#pragma unroll
            for (int q = 0; q < 4; q++) {
                float4 v = *(const float4*)(Xsrc + (size_t)m * K + kb + q * 4);
                av[q * 4] = v.x; av[q * 4 + 1] = v.y; av[q * 4 + 2] = v.z; av[q * 4 + 3] = v.w;
            }
            if (srow >= 0) {
#pragma unroll
                for (int q = 0; q < 4; q++) {
                    float4 v = *(const float4*)(xcur + (size_t)srow * K + kb + q * 4);
                    av[q * 4] += v.x; av[q * 4 + 1] += v.y;
                    av[q * 4 + 2] += v.z; av[q * 4 + 3] += v.w;
                }
            }
        }
        if (it + 1 < nt) {
            loadB((it + 1) & 1, (it + 1) * 32);
            asm volatile("cp.async.wait_group 1;\n" ::);
        } else {
            asm volatile("cp.async.wait_group 0;\n" ::);
        }
        __syncthreads();  // prev compute done -> Ahi writable; B stage visible
#pragma unroll
        for (int e = 0; e < 16; e++) {
            float v = av[e];
            bf16 h = __float2bfloat16(v);
            Ahi[arow * 40 + coff + e] = __bfloat16_as_ushort(h);
            Alo[arow * 40 + coff + e] =
                __bfloat16_as_ushort(__float2bfloat16(v - __bfloat162float(h)));
        }
        __syncthreads();
        const uint16_t* Bhi_s = Bst + (it & 1) * 2 * 5120;
        const uint16_t* Blo_s = Bhi_s + 5120;
#pragma unroll
        for (int ks = 0; ks < 32; ks += 16) {
            mma_block(Ahi, Bhi_s, ks, g, tg, wm, wn, acc);
            mma_block(Ahi, Blo_s, ks, g, tg, wm, wn, acc);
            mma_block(Alo, Bhi_s, ks, g, tg, wm, wn, acc);
        }
    }

#pragma unroll
    for (int mf = 0; mf < 4; mf++)
#pragma unroll
        for (int nf = 0; nf < 4; nf++)
#pragma unroll
            for (int e = 0; e < 4; e++) {
                int mm = m0 + wm * 64 + mf * 16 + g + (e >> 1) * 8;
                int c = j0 + wn * 32 + nf * 8 + 2 * tg + (e & 1);
                float v = acc[mf][nf][e];
                if (MODE == 1) {
                    v *= rsqrtf(scl[mm] + 2.f);
                    bf16 h = __float2bfloat16(v);
                    ((bf16*)Cp)[(size_t)c * n + mm] = h;
                    ((bf16*)C2p)[(size_t)c * n + mm] =
                        __float2bfloat16(v - __bfloat162float(h));
                } else {
                    ((float*)Cp)[(size_t)mm * 256 + c] = v * scl[mm];
                }
            }
}

// ---------------- host orchestration ----------------
#define SYM(p, s)                     \
    do {                              \
        void* _t = nullptr;           \
        cudaGetSymbolAddress(&_t, s); \
        p = (decltype(p))_t;          \
    } while (0)

extern "C" void kernel_launch(void* const* d_in, const int* in_sizes, int n_in,
                              void* d_out, int out_size) {
    const float* x_in = (const float*)d_in[0];
    const int* ei     = (const int*)d_in[1];
    const float* w_d0 = (const float*)d_in[3];
    const float* b_d0 = (const float*)d_in[4];
    const float* w_d  = (const float*)d_in[5];
    const float* b_d  = (const float*)d_in[6];
    const float* p_at = (const float*)d_in[7];
    const float* w_u  = (const float*)d_in[8];
    const float* b_u  = (const float*)d_in[9];
    float* out = (float*)d_out;
    const int E = in_sizes[1] / 2;

    bf16 *A1, *A2, *A3, *AT1, *AT2, *AT3, *WH, *WL, *zhi, *zlo;
    float *X0, *X1, *X2, *Xc, *Cpart, *zf, *A1f, *dinv0, *fil0, *sc, *pns, *mpart;
    int *zblk, *perm, *colmap, *rpi, *rpo, *cii, *cio, *curi, *curo;
    SYM(A1, g_A1);   SYM(A2, g_A2);   SYM(A3, g_A3);
    SYM(AT1, g_AT1); SYM(AT2, g_AT2); SYM(AT3, g_AT3);
    SYM(WH, g_WH);   SYM(WL, g_WL);
    SYM(zhi, g_zhi); SYM(zlo, g_zlo);
    SYM(X0, g_X0);   SYM(X1, g_X1);   SYM(X2, g_X2);
    SYM(Xc, g_Xc);   SYM(Cpart, g_Cpart);
    SYM(zf, g_z);    SYM(A1f, g_A1f);
    SYM(zblk, g_zblk);
    SYM(dinv0, g_dinv0); SYM(fil0, g_fil0);
    SYM(sc, g_s);    SYM(pns, g_pns); SYM(mpart, g_mpart);
    SYM(perm, g_perm); SYM(colmap, g_colmap);
    SYM(rpi, g_rpi); SYM(rpo, g_rpo); SYM(cii, g_cii); SYM(cio, g_cio);
    SYM(curi, g_curi); SYM(curo, g_curo);
    int* cnt = zblk;
    float* deg = (float*)(zblk + 3 * N0);

    cudaFuncSetAttribute(mma_gemm<2, 0>, cudaFuncAttributeMaxDynamicSharedMemorySize, 92160);
    cudaFuncSetAttribute(mma_gemm<1, 1>, cudaFuncAttributeMaxDynamicSharedMemorySize, 61440);
    cudaFuncSetAttribute(xw_gemm<2, 1>, cudaFuncAttributeMaxDynamicSharedMemorySize, 61440);
    cudaFuncSetAttribute(xw_gemm<2, 3>, cudaFuncAttributeMaxDynamicSharedMemorySize, 61440);
    cudaFuncSetAttribute(xw_gemm<1, 2>, cudaFuncAttributeMaxDynamicSharedMemorySize, 61440);
    cudaFuncSetAttribute(xw_gemm<1, 3>, cudaFuncAttributeMaxDynamicSharedMemorySize, 61440);

    bf16* Alv[4] = {nullptr, A1, A2, A3};
    bf16* ATlv[4] = {nullptr, AT1, AT2, AT3};
    float* Xs[3] = {X0, X1, X2};
    const int ns[4] = {4096, 2048, 1024, 512};

    // ---- setup ----
    cudaMemsetAsync(zblk, 0, 7 * N0 * sizeof(int));
    cudaMemsetAsync(colmap, 0xFF, 3 * N0 * sizeof(int));
    splitW_all<<<cdiv(32768 + 6 * 65536, 256), 256>>>(w_d0, w_d, w_u, WH, WL);
    count_deg<<<cdiv(E, 256), 256>>>(ei, E, cnt);
    scan_build<<<1, 1024>>>(cnt, rpi, rpo, curi, curo, dinv0, fil0, p_at, pns);
    fill_csr<<<cdiv(E, 256), 256>>>(ei, E, curi, curo, cii, cio);

    // dense GCN levels 1..3 (full score fused into reduce when pnext)
    auto gcn = [&](int lvl, int slot, const float* Xsrc, const int* pidx, int IN,
                   const float* bias, float* Y, int relu, const float* pnext) {
        int n = ns[lvl];
        if (IN == 2)
            xw_gemm<1, 2><<<dim3(2, n / 128), 256, 61440>>>(
                Xsrc, 256, nullptr, pidx, sc, pns + (lvl - 1), WH + slot * 65536,
                WL + slot * 65536, zhi, zlo, n, deg + lvl * N0);
        else
            xw_gemm<1, 3><<<dim3(2, n / 128), 256, 61440>>>(
                Xsrc, 256, Xc, pidx, nullptr, nullptr, WH + slot * 65536,
                WL + slot * 65536, zhi, zlo, n, deg + lvl * N0);
        mma_gemm<2, 0><<<dim3(2, n / 128, 8), 256, 92160>>>(
            ATlv[lvl], n, zhi, zlo, n, Cpart, 256, n / 8, (size_t)n * 256, nullptr);
        reduce_gcn<<<n, 256>>>(Cpart, 8, n * 256, n, zhi, zlo, deg + lvl * N0,
                               bias, Y, relu, pnext, sc);
    };

    // ---- level-0 down GCN (score fused into spmv) ----
    xw_gemm<2, 1><<<dim3(2, N0 / 128), 256, 61440>>>(
        x_in, 128, nullptr, nullptr, nullptr, nullptr, WH, WL, zf, nullptr, N0, dinv0);
    spmv_gcn<<<N0 / 8, 256>>>(rpi, cii, zf, dinv0, fil0, b_d0, X0, 1, p_at, sc);

    // ---- down path ----
    for (int i = 0; i < 3; i++) {
        int n = ns[i], k = ns[i + 1];
        int* pm = perm + i * 2048;
        int* cm = colmap + i * N0;

        if (i == 0) topk_select<4096><<<1, 1024>>>(sc, k, pm, cm);
        else if (i == 1) topk_select<2048><<<1, 1024>>>(sc, k, pm, cm);
        else topk_select<1024><<<1, 1024>>>(sc, k, pm, cm);

        if (i == 0) {
            cudaMemsetAsync(A1f, 0, (size_t)k * k * sizeof(float));
            sparse_augment<<<k, 256>>>(pm, cm, rpo, cio, A1f, k);
            finalize_A1<<<dim3(k / 64, k / 64), 256>>>(A1f, A1, AT1, deg + N0, k);
        } else {
            mma_gemm<1, 1><<<dim3(k / 128, k / 128, 4), 256, 61440>>>(
                Alv[i], n, ATlv[i], nullptr, n, A1f, k, n / 4, (size_t)k * k, pm);
            finalize_aug<<<dim3(k / 64, k / 64), 256>>>(A1f, Alv[i], pm, k, n,
                                                        Alv[i + 1], ATlv[i + 1],
                                                        deg + (i + 1) * N0);
        }

        float* Y = (i < 2) ? Xs[i + 1] : Xc;
        const float* pnext = (i < 2) ? (p_at + (i + 1) * CH) : nullptr;
        gcn(i + 1, 1 + i, Xs[i], pm, 2, b_d + i * CH, Y, 1, pnext);
    }

    // ---- up path ----
    for (int i = 0; i < 3; i++) {
        int j = 2 - i;
        if (j == 0) {
            xw_gemm<2, 3><<<dim3(2, N0 / 128), 256, 61440>>>(
                X0, 256, Xc, colmap, nullptr, nullptr,
                WH + (4 + i) * 65536, WL + (4 + i) * 65536, zf, nullptr, N0, dinv0);
            spmv_gcn<<<N0 / 8, 256>>>(rpi, cii, zf, dinv0, fil0, b_u + i * CH, Xc, 0,
                                      nullptr, nullptr);
        } else {
            gcn(j, 4 + i, Xs[j], colmap + j * N0, 3, b_u + i * CH, Xc, 1, nullptr);
        }
    }

    mean_part<<<32, 256>>>(Xc, mpart);
    mean_final<<<1, 256>>>(mpart, out);
}

// round 15
// speedup vs baseline: 1.0590x; 1.0443x over previous
#include <cuda_runtime.h>
#include <cuda_bf16.h>
#include <math.h>
#include <stdint.h>

#define N0 4096
#define CH 256
#define EMAX 131072

using bf16 = __nv_bfloat16;

// ---------------- scratch ----------------
__device__ bf16  g_A1[2048 * 2048];
__device__ bf16  g_A2[1024 * 1024];
__device__ bf16  g_A3[512 * 512];
__device__ bf16  g_AT1[2048 * 2048];
__device__ bf16  g_AT2[1024 * 1024];
__device__ bf16  g_AT3[512 * 512];
__device__ float g_A1f[2048 * 2048];   // augment split-K slices
__device__ float g_X0[N0 * CH];
__device__ float g_X1[2048 * CH];
__device__ float g_X2[1024 * CH];
__device__ float g_Xc[N0 * CH];
__device__ float g_z[N0 * CH];
__device__ bf16  g_WH[7 * 65536];
__device__ bf16  g_WL[7 * 65536];
__device__ bf16  g_zhi[CH * N0];
__device__ bf16  g_zlo[CH * N0];
__device__ float g_Cpart[8 * 2048 * CH];
__device__ int   g_zblk[7 * N0];       // [cnt: 3*N0 | deg: 4*N0(as float)]
__device__ float g_dinv0[N0];
__device__ float g_fil0[N0];
__device__ float g_s[N0];
__device__ float g_pns[3];
__device__ int   g_perm[3][2048];
__device__ int   g_colmap[3][N0];
__device__ int g_rpi[N0 + 1], g_rpo[N0 + 1];
__device__ int g_cii[EMAX], g_cio[EMAX];
__device__ int g_curi[N0], g_curo[N0];
__device__ float g_mpart[512 * 256];

static inline int cdiv(int a, int b) { return (a + b - 1) / b; }

// ---------------- CSR build ----------------
__global__ void count_deg(const int* __restrict__ ei, int E, int* __restrict__ cnt) {
    int i = blockIdx.x * blockDim.x + threadIdx.x;
    if (i >= E) return;
    int s = ei[i], d = ei[E + i];
    atomicAdd(cnt + N0 + s, 1);
    atomicAdd(cnt + d, 1);
    if (s == d) atomicAdd(cnt + 2 * N0 + s, 1);
}

__device__ void scan4096(const int* __restrict__ cnt, int* __restrict__ rp,
                         int* __restrict__ cur, int* loc) {
    int t = threadIdx.x;
    int base = t * 4;
    int v0 = cnt[base], v1 = cnt[base + 1], v2 = cnt[base + 2], v3 = cnt[base + 3];
    int s01 = v0 + v1;
    int s = s01 + v2 + v3;
    loc[t] = s;
    __syncthreads();
    for (int o = 1; o < 1024; o <<= 1) {
        int x = (t >= o) ? loc[t - o] : 0;
        __syncthreads();
        loc[t] += x;
        __syncthreads();
    }
    int excl = loc[t] - s;
    rp[base] = excl;           cur[base] = excl;
    rp[base + 1] = excl + v0;  cur[base + 1] = excl + v0;
    rp[base + 2] = excl + s01; cur[base + 2] = excl + s01;
    rp[base + 3] = excl + s01 + v2; cur[base + 3] = excl + s01 + v2;
    if (t == 1023) rp[4096] = excl + s;
}

__global__ void scan_build(const int* __restrict__ cnt,
                           int* rpi, int* rpo, int* curi, int* curo,
                           float* __restrict__ dinv, float* __restrict__ fil,
                           const float* __restrict__ p_at, float* __restrict__ pns) {
    __shared__ int loc[1024];
    scan4096(cnt, rpi, curi, loc);
    __syncthreads();
    scan4096(cnt + N0, rpo, curo, loc);
    int t = threadIdx.x;
#pragma unroll
    for (int q = 0; q < 4; q++) {
        int c = t * 4 + q;
        float f = (cnt[2 * N0 + c] == 0) ? 2.f : 0.f;
        fil[c] = f;
        dinv[c] = rsqrtf((float)cnt[c] + f);
    }
    if (t < 96) {
        int w = t >> 5, lane = t & 31;
        float a = 0.f;
#pragma unroll
        for (int q = 0; q < 8; q++) {
            float v = p_at[w * 256 + lane + 32 * q];
            a += v * v;
        }
#pragma unroll
        for (int o = 16; o; o >>= 1) a += __shfl_down_sync(0xffffffffu, a, o);
        if (lane == 0) pns[w] = rsqrtf(a);
    }
}

__global__ void fill_csr(const int* __restrict__ ei, int E, int* curi, int* curo,
                         int* __restrict__ cii, int* __restrict__ cio) {
    int i = blockIdx.x * blockDim.x + threadIdx.x;
    if (i >= E) return;
    int s = ei[i], d = ei[E + i];
    int po = atomicAdd(curo + s, 1);
    cio[po] = d;
    int pi = atomicAdd(curi + d, 1);
    cii[pi] = s;
}

__global__ void splitW_all(const float* __restrict__ w_d0, const float* __restrict__ w_d,
                           const float* __restrict__ w_u, bf16* __restrict__ hi,
                           bf16* __restrict__ lo) {
    int idx = blockIdx.x * blockDim.x + threadIdx.x;
    float v;
    int o;
    if (idx < 32768) {
        int k = idx >> 8, c = idx & 255;
        v = w_d0[idx];
        o = c * 128 + k;
    } else {
        int t = idx - 32768;
        if (t >= 6 * 65536) return;
        int mat = t >> 16, e = t & 65535;
        int k = e >> 8, c = e & 255;
        v = (mat < 3) ? w_d[mat * 65536 + e] : w_u[(mat - 3) * 65536 + e];
        o = (1 + mat) * 65536 + c * 256 + k;
    }
    bf16 h = __float2bfloat16(v);
    hi[o] = h;
    lo[o] = __float2bfloat16(v - __bfloat162float(h));
}

// sparse GCN + optional fused score (p) + optional fused mean partials (mpart).
// mpart partials are deterministic: per-warp smem rows, fixed-order reduction.
__global__ void spmv_gcn(const int* __restrict__ rp, const int* __restrict__ ci,
                         const float* __restrict__ z, const float* __restrict__ dinv,
                         const float* __restrict__ fil, const float* __restrict__ bias,
                         float* __restrict__ Y, int relu,
                         const float* __restrict__ p, float* __restrict__ scout,
                         float* __restrict__ mpart) {
    __shared__ float mp[8][256];
    int wid = threadIdx.x >> 5;
    int c = blockIdx.x * 8 + wid;
    int lane = threadIdx.x & 31;
    float acc[8] = {0.f, 0.f, 0.f, 0.f, 0.f, 0.f, 0.f, 0.f};
    int e0 = rp[c], e1 = rp[c + 1];
    for (int e = e0; e < e1; e++) {
        int r = ci[e];
        const float4* zp = (const float4*)(z + (size_t)r * CH + lane * 8);
        float4 a = zp[0], b = zp[1];
        acc[0] += a.x; acc[1] += a.y; acc[2] += a.z; acc[3] += a.w;
        acc[4] += b.x; acc[5] += b.y; acc[6] += b.z; acc[7] += b.w;
    }
    const float4* zc = (const float4*)(z + (size_t)c * CH + lane * 8);
    float4 za = zc[0], zb = zc[1];
    float zv[8] = {za.x, za.y, za.z, za.w, zb.x, zb.y, zb.z, zb.w};
    float f = fil[c], dv = dinv[c];
    float* yo = Y + (size_t)c * CH + lane * 8;
    float dot = 0.f;
#pragma unroll
    for (int q = 0; q < 8; q++) {
        float v = dv * (acc[q] + f * zv[q]) + bias[lane * 8 + q];
        if (relu) v = fmaxf(v, 0.f);
        yo[q] = v;
        if (p) dot += v * p[lane * 8 + q];
        if (mpart) mp[wid][lane * 8 + q] = v;
    }
    if (p) {
#pragma unroll
        for (int o = 16; o; o >>= 1) dot += __shfl_down_sync(0xffffffffu, dot, o);
        if (lane == 0) scout[c] = dot;
    }
    if (mpart) {
        __syncthreads();
        float s = 0.f;
#pragma unroll
        for (int w = 0; w < 8; w++) s += mp[w][threadIdx.x];
        mpart[(size_t)blockIdx.x * 256 + threadIdx.x] = s;
    }
}

// sparse (A+I)^2 restricted to kept rows/cols (global atomics; A1f pre-zeroed)
__global__ void sparse_augment(const int* __restrict__ pm, const int* __restrict__ colmap,
                               const int* __restrict__ rp, const int* __restrict__ ci,
                               float* __restrict__ A1f, int k) {
    int i = blockIdx.x;
    int pi = pm[i];
    int warp = threadIdx.x >> 5, lane = threadIdx.x & 31;
    float* row = A1f + (size_t)i * k;
    int b0 = rp[pi], b1 = rp[pi + 1];
    for (int e = b0 + threadIdx.x; e < b1; e += 256) {
        int j = colmap[ci[e]];
        if (j >= 0) atomicAdd(row + j, 2.f);
    }
    for (int e1 = b0 + warp; e1 < b1; e1 += 8) {
        int c = ci[e1];
        int c0 = rp[c], c1 = rp[c + 1];
        for (int e2 = c0 + lane; e2 < c1; e2 += 32) {
            int j = colmap[ci[e2]];
            if (j >= 0) atomicAdd(row + j, 1.f);
        }
    }
}

__global__ void finalize_A1(const float* __restrict__ Af, bf16* __restrict__ A,
                            bf16* __restrict__ AT, float* __restrict__ deg, int k) {
    __shared__ float t[64][65];
    int bx = blockIdx.x * 64, by = blockIdx.y * 64;
    int tid = threadIdx.x;
#pragma unroll
    for (int q = 0; q < 16; q++) {
        int s = q * 256 + tid;
        int r = s >> 6, c = s & 63;
        float v = Af[(size_t)(by + r) * k + bx + c];
        if (by + r == bx + c) v = 0.f;
        A[(size_t)(by + r) * k + bx + c] = __float2bfloat16(v);
        t[r][c] = v;
    }
    __syncthreads();
#pragma unroll
    for (int q = 0; q < 16; q++) {
        int s = q * 256 + tid;
        int r = s >> 6, c = s & 63;
        AT[(size_t)(bx + r) * k + by + c] = __float2bfloat16(t[c][r]);
    }
    if (tid < 64) {
        float s = 0.f;
#pragma unroll
        for (int r = 0; r < 64; r++) s += t[r][tid];
        atomicAdd(deg + bx + tid, s);
    }
}

// sum 4 split-K slices + 2*Aprev[pm[r],pm[c]], zero diag, colsum, emit A + AT
__global__ void finalize_aug(const float* __restrict__ Af, const bf16* __restrict__ Aprev,
                             const int* __restrict__ pm, int k, int nprev,
                             bf16* __restrict__ A, bf16* __restrict__ AT,
                             float* __restrict__ deg) {
    __shared__ float t[64][65];
    __shared__ int pmc[64], pmr[64];
    int bx = blockIdx.x * 64, by = blockIdx.y * 64;
    int tid = threadIdx.x;
    if (tid < 64) pmc[tid] = pm[bx + tid];
    else if (tid < 128) pmr[tid - 64] = pm[by + tid - 64];
    __syncthreads();
    size_t kk = (size_t)k * k;
#pragma unroll
    for (int q = 0; q < 16; q++) {
        int s = q * 256 + tid;
        int r = s >> 6, c = s & 63;
        size_t off = (size_t)(by + r) * k + bx + c;
        float v = Af[off] + Af[kk + off] + Af[2 * kk + off] + Af[3 * kk + off] +
                  2.f * __bfloat162float(Aprev[(size_t)pmr[r] * nprev + pmc[c]]);
        if (by + r == bx + c) v = 0.f;
        A[off] = __float2bfloat16(v);
        t[r][c] = v;
    }
    __syncthreads();
#pragma unroll
    for (int q = 0; q < 16; q++) {
        int s = q * 256 + tid;
        int r = s >> 6, c = s & 63;
        AT[(size_t)(bx + r) * k + by + c] = __float2bfloat16(t[c][r]);
    }
    if (tid < 64) {
        float s = 0.f;
#pragma unroll
        for (int r = 0; r < 64; r++) s += t[r][tid];
        atomicAdd(deg + bx + tid, s);
    }
}

// ---------------- single-block BYTE-RADIX top-k select ----------------
// 4 histogram rounds find theta (k-th largest key) and need_eq; then
// index-ordered compaction (identical selected set to jax top_k; perm in
// ascending-index order; deterministic).
template <int SZ>
__global__ void topk_select(const float* __restrict__ s0, int k,
                            int* __restrict__ perm, int* __restrict__ colmap) {
    constexpr int PT = SZ / 1024;
    __shared__ uint32_t key[SZ];
    __shared__ int hist[256];
    __shared__ int loc[1024];
    __shared__ uint32_t sh_theta;
    __shared__ int sh_need;
    int tid = threadIdx.x;
#pragma unroll
    for (int q = 0; q < PT; q++) {
        int t = tid * PT + q;
        uint32_t b = __float_as_uint(s0[t]);
        key[t] = (b & 0x80000000u) ? ~b : (b | 0x80000000u);
    }
    if (tid == 0) { sh_theta = 0; sh_need = k; }
    __syncthreads();

    for (int round = 0; round < 4; round++) {
        int shift = 24 - 8 * round;
        uint32_t theta = sh_theta;
        int need = sh_need;
        uint32_t hi_mask = (round == 0) ? 0u : (0xFFFFFFFFu << (shift + 8));
        if (tid < 256) hist[tid] = 0;
        __syncthreads();
#pragma unroll
        for (int q = 0; q < PT; q++) {
            uint32_t kv = key[tid * PT + q];
            if (((kv ^ theta) & hi_mask) == 0)
                atomicAdd(&hist[(kv >> shift) & 255], 1);
        }
        __syncthreads();
        if (tid < 32) {
            int base = tid * 8;
            int v[8], suf[8];
            int run = 0;
#pragma unroll
            for (int j = 7; j >= 0; j--) {
                v[j] = hist[base + j];
                run += v[j];
                suf[j] = run;
            }
            int acc = run;
#pragma unroll
            for (int o = 1; o < 32; o <<= 1) {
                int x = __shfl_down_sync(0xffffffffu, acc, o);
                if (tid + o < 32) acc += x;
            }
            int excl = acc - run;  // sum of totals in lanes > tid
#pragma unroll
            for (int j = 0; j < 8; j++) {
                int gt = excl + suf[j] - v[j];
                if (gt < need && gt + v[j] >= need) {
                    sh_theta = theta | ((uint32_t)(base + j) << shift);
                    sh_need = need - gt;
                }
            }
        }
        __syncthreads();
    }
    const uint32_t theta = sh_theta;
    const int need_eq = sh_need;

    // index-ordered compaction: packed (gt | eq<<16) exclusive scan
    int sloc = 0;
#pragma unroll
    for (int q = 0; q < PT; q++) {
        uint32_t kv = key[tid * PT + q];
        sloc += (kv > theta) ? 1 : ((kv == theta) ? 65536 : 0);
    }
    loc[tid] = sloc;
    __syncthreads();
    for (int o = 1; o < 1024; o <<= 1) {
        int x = (tid >= o) ? loc[tid - o] : 0;
        __syncthreads();
        loc[tid] += x;
        __syncthreads();
    }
    int pref = loc[tid] - sloc;
    int gtp = pref & 0xffff, eqp = pref >> 16;
#pragma unroll
    for (int q = 0; q < PT; q++) {
        int i = tid * PT + q;
        uint32_t kv = key[i];
        bool gt = kv > theta;
        bool eq = (kv == theta);
        bool sel = gt || (eq && eqp < need_eq);
        if (sel) {
            int pos = gtp + (eqp < need_eq ? eqp : need_eq);
            perm[pos] = i;
            colmap[i] = pos;
        }
        gtp += gt;
        eqp += eq;
    }
}

__global__ void mean_final(const float* __restrict__ part, float* __restrict__ out) {
    int j = threadIdx.x;
    float s = 0.f;
    for (int b = 0; b < 512; b++) s += part[(size_t)b * 256 + j];
    out[j] = s / (float)N0;
}

// GCN final reduce over split-K partials + optional fused FULL score.
__global__ void reduce_gcn(const float* __restrict__ part, int S, int partStride, int M,
                           const bf16* __restrict__ zh, const bf16* __restrict__ zl,
                           const float* __restrict__ deg,
                           const float* __restrict__ bias, float* __restrict__ Y, int relu,
                           const float* __restrict__ p, float* __restrict__ scout) {
    int m = blockIdx.x, c = threadIdx.x;
    size_t idx = (size_t)m * 256 + c;
    float s = 0.f;
    for (int q = 0; q < S; q++) s += part[(size_t)q * partStride + idx];
    float z = __bfloat162float(zh[(size_t)c * M + m]) + __bfloat162float(zl[(size_t)c * M + m]);
    float dv = rsqrtf(deg[m] + 2.f);
    float v = dv * (s + 2.f * z) + bias[c];
    if (relu) v = fmaxf(v, 0.f);
    Y[idx] = v;
    if (p) {
        __shared__ float red[8];
        float d = v * p[c];
#pragma unroll
        for (int o = 16; o; o >>= 1) d += __shfl_down_sync(0xffffffffu, d, o);
        if ((c & 31) == 0) red[c >> 5] = d;
        __syncthreads();
        if (c < 8) {
            float a = red[c];
#pragma unroll
            for (int o = 4; o; o >>= 1) a += __shfl_down_sync(0xffu, a, o);
            if (c == 0) scout[m] = a;
        }
    }
}

// ---------------- shared tile loader (bf16, cp.async) ----------------
template <int G>
__device__ __forceinline__ void ld_tile(const bf16* __restrict__ src, int ld,
                                        int row0, int k0, uint16_t* dst, int tid,
                                        const int* __restrict__ pm) {
#pragma unroll
    for (int i = 0; i < 2; i++) {
        int s = tid + i * 256;
        int r = s >> 2, c8 = (s & 3) * 8;
        int row = row0 + r;
        if (G) row = pm[row];
        const bf16* g = src + (size_t)row * ld + k0 + c8;
        uint32_t sm = (uint32_t)__cvta_generic_to_shared(dst + r * 40 + c8);
        asm volatile("cp.async.ca.shared.global [%0], [%1], 16;\n" ::"r"(sm), "l"(g));
    }
}

// ---------------- MMA compute helper ----------------
__device__ __forceinline__ void mma_block(const uint16_t* Asb, const uint16_t* Bsb,
                                          int ks, int g, int tg, int wm, int wn,
                                          float acc[4][4][4]) {
    uint32_t af[4][4], bfr[4][2];
    const int kc = ks + 2 * tg;
#pragma unroll
    for (int mf = 0; mf < 4; mf++) {
        int m = wm * 64 + mf * 16 + g;
        af[mf][0] = *(const uint32_t*)&Asb[m * 40 + kc];
        af[mf][1] = *(const uint32_t*)&Asb[(m + 8) * 40 + kc];
        af[mf][2] = *(const uint32_t*)&Asb[m * 40 + kc + 8];
        af[mf][3] = *(const uint32_t*)&Asb[(m + 8) * 40 + kc + 8];
    }
#pragma unroll
    for (int nf = 0; nf < 4; nf++) {
        int n = wn * 32 + nf * 8 + g;
        bfr[nf][0] = *(const uint32_t*)&Bsb[n * 40 + kc];
        bfr[nf][1] = *(const uint32_t*)&Bsb[n * 40 + kc + 8];
    }
#pragma unroll
    for (int mf = 0; mf < 4; mf++)
#pragma unroll
        for (int nf = 0; nf < 4; nf++)
            asm volatile(
                "mma.sync.aligned.m16n8k16.row.col.f32.bf16.bf16.f32 "
                "{%0,%1,%2,%3},{%4,%5,%6,%7},{%8,%9},{%0,%1,%2,%3};"
                : "+f"(acc[mf][nf][0]), "+f"(acc[mf][nf][1]),
                  "+f"(acc[mf][nf][2]), "+f"(acc[mf][nf][3])
                : "r"(af[mf][0]), "r"(af[mf][1]), "r"(af[mf][2]),
                  "r"(af[mf][3]), "r"(bfr[nf][0]), "r"(bfr[nf][1]));
}

// ---------------- bf16-operand GEMM, 3-STAGE pipeline ----------------
template <int NPROD, int G>
__global__ void __launch_bounds__(256, 2) mma_gemm(
    const bf16* __restrict__ A0p, int lda,
    const bf16* __restrict__ B0p, const bf16* __restrict__ B1p, int ldb,
    float* __restrict__ Cp, int ldc, int ksplit, size_t partStride,
    const int* __restrict__ pm) {
    constexpr int PB = (NPROD >= 2) ? 2 : 1;
    constexpr int TS = 128 * 40;            // u16 per tile
    constexpr int SS = (1 + PB) * TS;       // u16 per stage
    extern __shared__ __align__(16) uint16_t sh[];

    const int tid = threadIdx.x;
    const int lane = tid & 31, warp = tid >> 5;
    const int g = lane >> 2, tg = lane & 3;
    const int wm = warp >> 2, wn = warp & 3;
    const int m0 = blockIdx.y * 128, j0 = blockIdx.x * 128;

    float acc[4][4][4];
#pragma unroll
    for (int a = 0; a < 4; a++)
#pragma unroll
        for (int b = 0; b < 4; b++)
#pragma unroll
            for (int e = 0; e < 4; e++) acc[a][b][e] = 0.f;

    auto load_stage = [&](int st, int k0) {
        ld_tile<G>(A0p, lda, m0, k0, sh + st * SS, tid, pm);
        ld_tile<G>(B0p, ldb, j0, k0, sh + st * SS + TS, tid, pm);
        if (PB == 2) ld_tile<G>(B1p, ldb, j0, k0, sh + st * SS + 2 * TS, tid, pm);
        asm volatile("cp.async.commit_group;\n" ::);
    };

    const int kb = blockIdx.z * ksplit;
    const int nt = ksplit / 32;

    load_stage(0, kb);
    if (nt > 1) load_stage(1, kb + 32);
    int st = 0;
    for (int it = 0; it < nt; it++) {
        if (it + 1 < nt)
            asm volatile("cp.async.wait_group 1;\n" ::);
        else
            asm volatile("cp.async.wait_group 0;\n" ::);
        __syncthreads();  // stage st ready; compute(it-1) readers done
        if (it + 2 < nt) load_stage((st + 2) % 3, kb + (it + 2) * 32);
        const uint16_t* As = sh + st * SS;
        const uint16_t* Bs0 = As + TS;
#pragma unroll
        for (int ks = 0; ks < 32; ks += 16)
            mma_block(As, Bs0, ks, g, tg, wm, wn, acc);
        if (PB == 2) {
            const uint16_t* Bs1 = As + 2 * TS;
#pragma unroll
            for (int ks = 0; ks < 32; ks += 16)
                mma_block(As, Bs1, ks, g, tg, wm, wn, acc);
        }
        st = (st + 1) % 3;
    }

#pragma unroll
    for (int mf = 0; mf < 4; mf++)
#pragma unroll
        for (int nf = 0; nf < 4; nf++)
#pragma unroll
            for (int e = 0; e < 4; e++) {
                int m = m0 + wm * 64 + mf * 16 + g + (e >> 1) * 8;
                int c = j0 + wn * 32 + nf * 8 + 2 * tg + (e & 1);
                Cp[(size_t)blockIdx.z * partStride + (size_t)m * ldc + c] = acc[mf][nf][e];
            }
}

// ---------------- fused XW GEMM (proven pipeline) ----------------
// IN=1: A = Xsrc[m][k]
// IN=2: A = Xsrc[idx[m]][k] * tanh(s[idx[m]]*pn)
// IN=3: A = Xsrc[m][k] + (idx[m]>=0 ? xcur[idx[m]][k] : 0)
// MODE=1: z = rsqrt(scl[m]+2)*acc -> zhi/zlo transposed [c*n+m]
// MODE=2: z = scl[m]*acc -> fp32 [m*256+c]
template <int MODE, int IN>
__global__ void __launch_bounds__(256, 2) xw_gemm(
    const float* __restrict__ Xsrc, int K,
    const float* __restrict__ xcur, const int* __restrict__ idx,
    const float* __restrict__ s, const float* __restrict__ pn,
    const bf16* __restrict__ Bh, const bf16* __restrict__ Bl,
    void* __restrict__ Cp, void* __restrict__ C2p, int n,
    const float* __restrict__ scl) {
    extern __shared__ __align__(16) uint16_t sh[];
    uint16_t* Ahi = sh;
    uint16_t* Alo = sh + 5120;
    uint16_t* Bst = sh + 2 * 5120;

    const int tid = threadIdx.x;
    const int lane = tid & 31, warp = tid >> 5;
    const int g = lane >> 2, tg = lane & 3;
    const int wm = warp >> 2, wn = warp & 3;
    const int m0 = blockIdx.y * 128, j0 = blockIdx.x * 128;

    float acc[4][4][4];
#pragma unroll
    for (int a = 0; a < 4; a++)
#pragma unroll
        for (int b = 0; b < 4; b++)
#pragma unroll
            for (int e = 0; e < 4; e++) acc[a][b][e] = 0.f;

    auto loadB = [&](int st, int k0) {
        ld_tile<0>(Bh, K, j0, k0, Bst + st * 2 * 5120, tid, nullptr);
        ld_tile<0>(Bl, K, j0, k0, Bst + (st * 2 + 1) * 5120, tid, nullptr);
        asm volatile("cp.async.commit_group;\n" ::);
    };

    const int arow = tid >> 1;
    const int coff = (tid & 1) * 16;
    const int m = m0 + arow;
    int srow = 0;
    float gate = 1.f;
    if (IN == 2) {
        srow = idx[m];
        gate = tanhf(s[srow] * pn[0]);
    } else if (IN == 3) {
        srow = idx[m];
    }

    const int nt = K / 32;
    loadB(0, 0);
    for (int it = 0; it < nt; it++) {
        float av[16];
        int kb = it * 32 + coff;
        if (IN == 1) {
#pragma unroll
            for (int q = 0; q < 4; q++) {
                float4 v = *(const float4*)(Xsrc + (size_t)m * K + kb + q * 4);
                av[q * 4] = v.x; av[q * 4 + 1] = v.y; av[q * 4 + 2] = v.z; av[q * 4 + 3] = v.w;
            }
        } else if (IN == 2) {
#pragma unroll
            for (int q = 0; q < 4; q++) {
                float4 v = *(const float4*)(Xsrc + (size_t)srow * K + kb + q * 4);
                av[q * 4] = v.x * gate; av[q * 4 + 1] = v.y * gate;
                av[q * 4 + 2] = v.z * gate; av[q * 4 + 3] = v.w * gate;
            }
        } else {
#pragma unroll
            for (int q = 0; q < 4; q++) {
                float4 v = *(const float4*)(Xsrc + (size_t)m * K + kb + q * 4);
                av[q * 4] = v.x; av[q * 4 + 1] = v.y; av[q * 4 + 2] = v.z; av[q * 4 + 3] = v.w;
            }
            if (srow >= 0) {
#pragma unroll
                for (int q = 0; q < 4; q++) {
                    float4 v = *(const float4*)(xcur + (size_t)srow * K + kb + q * 4);
                    av[q * 4] += v.x; av[q * 4 + 1] += v.y;
                    av[q * 4 + 2] += v.z; av[q * 4 + 3] += v.w;
                }
            }
        }
        if (it + 1 < nt) {
            loadB((it + 1) & 1, (it + 1) * 32);
            asm volatile("cp.async.wait_group 1;\n" ::);
        } else {
            asm volatile("cp.async.wait_group 0;\n" ::);
        }
        __syncthreads();  // prev compute done -> Ahi writable; B stage visible
#pragma unroll
        for (int e = 0; e < 16; e++) {
            float v = av[e];
            bf16 h = __float2bfloat16(v);
            Ahi[arow * 40 + coff + e] = __bfloat16_as_ushort(h);
            Alo[arow * 40 + coff + e] =
                __bfloat16_as_ushort(__float2bfloat16(v - __bfloat162float(h)));
        }
        __syncthreads();
        const uint16_t* Bhi_s = Bst + (it & 1) * 2 * 5120;
        const uint16_t* Blo_s = Bhi_s + 5120;
#pragma unroll
        for (int ks = 0; ks < 32; ks += 16) {
            mma_block(Ahi, Bhi_s, ks, g, tg, wm, wn, acc);
            mma_block(Ahi, Blo_s, ks, g, tg, wm, wn, acc);
            mma_block(Alo, Bhi_s, ks, g, tg, wm, wn, acc);
        }
    }

#pragma unroll
    for (int mf = 0; mf < 4; mf++)
#pragma unroll
        for (int nf = 0; nf < 4; nf++)
#pragma unroll
            for (int e = 0; e < 4; e++) {
                int mm = m0 + wm * 64 + mf * 16 + g + (e >> 1) * 8;
                int c = j0 + wn * 32 + nf * 8 + 2 * tg + (e & 1);
                float v = acc[mf][nf][e];
                if (MODE == 1) {
                    v *= rsqrtf(scl[mm] + 2.f);
                    bf16 h = __float2bfloat16(v);
                    ((bf16*)Cp)[(size_t)c * n + mm] = h;
                    ((bf16*)C2p)[(size_t)c * n + mm] =
                        __float2bfloat16(v - __bfloat162float(h));
                } else {
                    ((float*)Cp)[(size_t)mm * 256 + c] = v * scl[mm];
                }
            }
}

// ---------------- host orchestration ----------------
#define SYM(p, s)                     \
    do {                              \
        void* _t = nullptr;           \
        cudaGetSymbolAddress(&_t, s); \
        p = (decltype(p))_t;          \
    } while (0)

extern "C" void kernel_launch(void* const* d_in, const int* in_sizes, int n_in,
                              void* d_out, int out_size) {
    const float* x_in = (const float*)d_in[0];
    const int* ei     = (const int*)d_in[1];
    const float* w_d0 = (const float*)d_in[3];
    const float* b_d0 = (const float*)d_in[4];
    const float* w_d  = (const float*)d_in[5];
    const float* b_d  = (const float*)d_in[6];
    const float* p_at = (const float*)d_in[7];
    const float* w_u  = (const float*)d_in[8];
    const float* b_u  = (const float*)d_in[9];
    float* out = (float*)d_out;
    const int E = in_sizes[1] / 2;

    bf16 *A1, *A2, *A3, *AT1, *AT2, *AT3, *WH, *WL, *zhi, *zlo;
    float *X0, *X1, *X2, *Xc, *Cpart, *zf, *A1f, *dinv0, *fil0, *sc, *pns, *mpart;
    int *zblk, *perm, *colmap, *rpi, *rpo, *cii, *cio, *curi, *curo;
    SYM(A1, g_A1);   SYM(A2, g_A2);   SYM(A3, g_A3);
    SYM(AT1, g_AT1); SYM(AT2, g_AT2); SYM(AT3, g_AT3);
    SYM(WH, g_WH);   SYM(WL, g_WL);
    SYM(zhi, g_zhi); SYM(zlo, g_zlo);
    SYM(X0, g_X0);   SYM(X1, g_X1);   SYM(X2, g_X2);
    SYM(Xc, g_Xc);   SYM(Cpart, g_Cpart);
    SYM(zf, g_z);    SYM(A1f, g_A1f);
    SYM(zblk, g_zblk);
    SYM(dinv0, g_dinv0); SYM(fil0, g_fil0);
    SYM(sc, g_s);    SYM(pns, g_pns); SYM(mpart, g_mpart);
    SYM(perm, g_perm); SYM(colmap, g_colmap);
    SYM(rpi, g_rpi); SYM(rpo, g_rpo); SYM(cii, g_cii); SYM(cio, g_cio);
    SYM(curi, g_curi); SYM(curo, g_curo);
    int* cnt = zblk;
    float* deg = (float*)(zblk + 3 * N0);

    cudaFuncSetAttribute(mma_gemm<2, 0>, cudaFuncAttributeMaxDynamicSharedMemorySize, 92160);
    cudaFuncSetAttribute(mma_gemm<1, 1>, cudaFuncAttributeMaxDynamicSharedMemorySize, 61440);
    cudaFuncSetAttribute(xw_gemm<2, 1>, cudaFuncAttributeMaxDynamicSharedMemorySize, 61440);
    cudaFuncSetAttribute(xw_gemm<2, 3>, cudaFuncAttributeMaxDynamicSharedMemorySize, 61440);
    cudaFuncSetAttribute(xw_gemm<1, 2>, cudaFuncAttributeMaxDynamicSharedMemorySize, 61440);
    cudaFuncSetAttribute(xw_gemm<1, 3>, cudaFuncAttributeMaxDynamicSharedMemorySize, 61440);

    bf16* Alv[4] = {nullptr, A1, A2, A3};
    bf16* ATlv[4] = {nullptr, AT1, AT2, AT3};
    float* Xs[3] = {X0, X1, X2};
    const int ns[4] = {4096, 2048, 1024, 512};

    // ---- setup ----
    cudaMemsetAsync(zblk, 0, 7 * N0 * sizeof(int));
    cudaMemsetAsync(colmap, 0xFF, 3 * N0 * sizeof(int));
    splitW_all<<<cdiv(32768 + 6 * 65536, 256), 256>>>(w_d0, w_d, w_u, WH, WL);
    count_deg<<<cdiv(E, 256), 256>>>(ei, E, cnt);
    scan_build<<<1, 1024>>>(cnt, rpi, rpo, curi, curo, dinv0, fil0, p_at, pns);
    fill_csr<<<cdiv(E, 256), 256>>>(ei, E, curi, curo, cii, cio);

    // dense GCN levels 1..3 (full score fused into reduce when pnext)
    auto gcn = [&](int lvl, int slot, const float* Xsrc, const int* pidx, int IN,
                   const float* bias, float* Y, int relu, const float* pnext) {
        int n = ns[lvl];
        if (IN == 2)
            xw_gemm<1, 2><<<dim3(2, n / 128), 256, 61440>>>(
                Xsrc, 256, nullptr, pidx, sc, pns + (lvl - 1), WH + slot * 65536,
                WL + slot * 65536, zhi, zlo, n, deg + lvl * N0);
        else
            xw_gemm<1, 3><<<dim3(2, n / 128), 256, 61440>>>(
                Xsrc, 256, Xc, pidx, nullptr, nullptr, WH + slot * 65536,
                WL + slot * 65536, zhi, zlo, n, deg + lvl * N0);
        mma_gemm<2, 0><<<dim3(2, n / 128, 8), 256, 92160>>>(
            ATlv[lvl], n, zhi, zlo, n, Cpart, 256, n / 8, (size_t)n * 256, nullptr);
        reduce_gcn<<<n, 256>>>(Cpart, 8, n * 256, n, zhi, zlo, deg + lvl * N0,
                               bias, Y, relu, pnext, sc);
    };

    // ---- level-0 down GCN (score fused into spmv) ----
    xw_gemm<2, 1><<<dim3(2, N0 / 128), 256, 61440>>>(
        x_in, 128, nullptr, nullptr, nullptr, nullptr, WH, WL, zf, nullptr, N0, dinv0);
    spmv_gcn<<<N0 / 8, 256>>>(rpi, cii, zf, dinv0, fil0, b_d0, X0, 1, p_at, sc, nullptr);

    // ---- down path ----
    for (int i = 0; i < 3; i++) {
        int n = ns[i], k = ns[i + 1];
        int* pm = perm + i * 2048;
        int* cm = colmap + i * N0;

        if (i == 0) topk_select<4096><<<1, 1024>>>(sc, k, pm, cm);
        else if (i == 1) topk_select<2048><<<1, 1024>>>(sc, k, pm, cm);
        else topk_select<1024><<<1, 1024>>>(sc, k, pm, cm);

        if (i == 0) {
            cudaMemsetAsync(A1f, 0, (size_t)k * k * sizeof(float));
            sparse_augment<<<k, 256>>>(pm, cm, rpo, cio, A1f, k);
            finalize_A1<<<dim3(k / 64, k / 64), 256>>>(A1f, A1, AT1, deg + N0, k);
        } else {
            mma_gemm<1, 1><<<dim3(k / 128, k / 128, 4), 256, 61440>>>(
                Alv[i], n, ATlv[i], nullptr, n, A1f, k, n / 4, (size_t)k * k, pm);
            finalize_aug<<<dim3(k / 64, k / 64), 256>>>(A1f, Alv[i], pm, k, n,
                                                        Alv[i + 1], ATlv[i + 1],
                                                        deg + (i + 1) * N0);
        }

        float* Y = (i < 2) ? Xs[i + 1] : Xc;
        const float* pnext = (i < 2) ? (p_at + (i + 1) * CH) : nullptr;
        gcn(i + 1, 1 + i, Xs[i], pm, 2, b_d + i * CH, Y, 1, pnext);
    }

    // ---- up path ----
    for (int i = 0; i < 3; i++) {
        int j = 2 - i;
        if (j == 0) {
            xw_gemm<2, 3><<<dim3(2, N0 / 128), 256, 61440>>>(
                X0, 256, Xc, colmap, nullptr, nullptr,
                WH + (4 + i) * 65536, WL + (4 + i) * 65536, zf, nullptr, N0, dinv0);
            // final GCN: fuse deterministic mean partials, skip mean_part pass
            spmv_gcn<<<N0 / 8, 256>>>(rpi, cii, zf, dinv0, fil0, b_u + i * CH, Xc, 0,
                                      nullptr, nullptr, mpart);
        } else {
            gcn(j, 4 + i, Xs[j], colmap + j * N0, 3, b_u + i * CH, Xc, 1, nullptr);
        }
    }

    mean_final<<<1, 256>>>(mpart, out);
}

// round 16
// speedup vs baseline: 1.0764x; 1.0165x over previous
#include <cuda_runtime.h>
#include <cuda_bf16.h>
#include <math.h>
#include <stdint.h>

#define N0 4096
#define CH 256
#define EMAX 131072

using bf16 = __nv_bfloat16;

// ---------------- scratch ----------------
__device__ bf16  g_A1[2048 * 2048];
__device__ bf16  g_A2[1024 * 1024];
__device__ bf16  g_A3[512 * 512];
__device__ bf16  g_AT1[2048 * 2048];
__device__ bf16  g_AT2[1024 * 1024];
__device__ bf16  g_AT3[512 * 512];
__device__ float g_A1f[2048 * 2048];   // augment split-K slices
__device__ float g_X0[N0 * CH];
__device__ float g_X1[2048 * CH];
__device__ float g_X2[1024 * CH];
__device__ float g_Xc[N0 * CH];
__device__ float g_z[N0 * CH];
__device__ bf16  g_WH[7 * 65536];
__device__ bf16  g_WL[7 * 65536];
__device__ bf16  g_zhi[CH * N0];
__device__ bf16  g_zlo[CH * N0];
__device__ float g_Cpart[8 * 2048 * CH];
__device__ int   g_zblk[7 * N0];       // [cnt: 3*N0 | deg: 4*N0(as float)]
__device__ float g_dinv0[N0];
__device__ float g_fil0[N0];
__device__ float g_s[N0];
__device__ float g_pns[3];
__device__ int   g_perm[3][2048];
__device__ int   g_colmap[3][N0];
__device__ int g_rpi[N0 + 1], g_rpo[N0 + 1];
__device__ int g_cii[EMAX], g_cio[EMAX];
__device__ int g_curi[N0], g_curo[N0];
__device__ float g_mpart[512 * 256];

static inline int cdiv(int a, int b) { return (a + b - 1) / b; }

#define NWSPLIT (32768 + 6 * 65536)  // 425984 weight elements

// ---------------- fused setup: weight split + zblk zero + colmap fill ----------------
__global__ void setup_all(const float* __restrict__ w_d0, const float* __restrict__ w_d,
                          const float* __restrict__ w_u, bf16* __restrict__ hi,
                          bf16* __restrict__ lo, int* __restrict__ zblk,
                          int* __restrict__ colmap) {
    int idx = blockIdx.x * blockDim.x + threadIdx.x;
    if (idx < NWSPLIT) {
        float v;
        int o;
        if (idx < 32768) {
            int k = idx >> 8, c = idx & 255;
            v = w_d0[idx];
            o = c * 128 + k;
        } else {
            int t = idx - 32768;
            int mat = t >> 16, e = t & 65535;
            int k = e >> 8, c = e & 255;
            v = (mat < 3) ? w_d[mat * 65536 + e] : w_u[(mat - 3) * 65536 + e];
            o = (1 + mat) * 65536 + c * 256 + k;
        }
        bf16 h = __float2bfloat16(v);
        hi[o] = h;
        lo[o] = __float2bfloat16(v - __bfloat162float(h));
    } else if (idx < NWSPLIT + 7 * N0) {
        zblk[idx - NWSPLIT] = 0;
    } else if (idx < NWSPLIT + 7 * N0 + 3 * N0) {
        colmap[idx - NWSPLIT - 7 * N0] = -1;
    }
}

// ---------------- CSR build ----------------
__global__ void count_deg(const int* __restrict__ ei, int E, int* __restrict__ cnt) {
    int i = blockIdx.x * blockDim.x + threadIdx.x;
    if (i >= E) return;
    int s = ei[i], d = ei[E + i];
    atomicAdd(cnt + N0 + s, 1);
    atomicAdd(cnt + d, 1);
    if (s == d) atomicAdd(cnt + 2 * N0 + s, 1);
}

// hierarchical warp-shfl scan (3 syncs); wsum needs 33 ints
__device__ void scan4096(const int* __restrict__ cnt, int* __restrict__ rp,
                         int* __restrict__ cur, int* wsum) {
    int t = threadIdx.x, lane = t & 31, w = t >> 5;
    int base = t * 4;
    int v0 = cnt[base], v1 = cnt[base + 1], v2 = cnt[base + 2], v3 = cnt[base + 3];
    int s01 = v0 + v1;
    int s = s01 + v2 + v3;
    int inc = s;
#pragma unroll
    for (int o = 1; o < 32; o <<= 1) {
        int x = __shfl_up_sync(0xffffffffu, inc, o);
        if (lane >= o) inc += x;
    }
    if (lane == 31) wsum[w] = inc;
    __syncthreads();
    if (w == 0) {
        int ws = wsum[lane];
        int winc = ws;
#pragma unroll
        for (int o = 1; o < 32; o <<= 1) {
            int x = __shfl_up_sync(0xffffffffu, winc, o);
            if (lane >= o) winc += x;
        }
        if (lane == 31) wsum[32] = winc;
        wsum[lane] = winc - ws;  // exclusive per-warp offset
    }
    __syncthreads();
    int excl = wsum[w] + inc - s;
    rp[base] = excl;           cur[base] = excl;
    rp[base + 1] = excl + v0;  cur[base + 1] = excl + v0;
    rp[base + 2] = excl + s01; cur[base + 2] = excl + s01;
    rp[base + 3] = excl + s01 + v2; cur[base + 3] = excl + s01 + v2;
    if (t == 1023) rp[4096] = wsum[32];
    __syncthreads();  // wsum reusable by caller
}

__global__ void scan_build(const int* __restrict__ cnt,
                           int* rpi, int* rpo, int* curi, int* curo,
                           float* __restrict__ dinv, float* __restrict__ fil,
                           const float* __restrict__ p_at, float* __restrict__ pns) {
    __shared__ int wsum[33];
    scan4096(cnt, rpi, curi, wsum);
    scan4096(cnt + N0, rpo, curo, wsum);
    int t = threadIdx.x;
#pragma unroll
    for (int q = 0; q < 4; q++) {
        int c = t * 4 + q;
        float f = (cnt[2 * N0 + c] == 0) ? 2.f : 0.f;
        fil[c] = f;
        dinv[c] = rsqrtf((float)cnt[c] + f);
    }
    if (t < 96) {
        int w = t >> 5, lane = t & 31;
        float a = 0.f;
#pragma unroll
        for (int q = 0; q < 8; q++) {
            float v = p_at[w * 256 + lane + 32 * q];
            a += v * v;
        }
#pragma unroll
        for (int o = 16; o; o >>= 1) a += __shfl_down_sync(0xffffffffu, a, o);
        if (lane == 0) pns[w] = rsqrtf(a);
    }
}

__global__ void fill_csr(const int* __restrict__ ei, int E, int* curi, int* curo,
                         int* __restrict__ cii, int* __restrict__ cio) {
    int i = blockIdx.x * blockDim.x + threadIdx.x;
    if (i >= E) return;
    int s = ei[i], d = ei[E + i];
    int po = atomicAdd(curo + s, 1);
    cio[po] = d;
    int pi = atomicAdd(curi + d, 1);
    cii[pi] = s;
}

// sparse GCN + optional fused score (p) + optional fused mean partials (mpart).
__global__ void spmv_gcn(const int* __restrict__ rp, const int* __restrict__ ci,
                         const float* __restrict__ z, const float* __restrict__ dinv,
                         const float* __restrict__ fil, const float* __restrict__ bias,
                         float* __restrict__ Y, int relu,
                         const float* __restrict__ p, float* __restrict__ scout,
                         float* __restrict__ mpart) {
    __shared__ float mp[8][256];
    int wid = threadIdx.x >> 5;
    int c = blockIdx.x * 8 + wid;
    int lane = threadIdx.x & 31;
    float acc[8] = {0.f, 0.f, 0.f, 0.f, 0.f, 0.f, 0.f, 0.f};
    int e0 = rp[c], e1 = rp[c + 1];
    for (int e = e0; e < e1; e++) {
        int r = ci[e];
        const float4* zp = (const float4*)(z + (size_t)r * CH + lane * 8);
        float4 a = zp[0], b = zp[1];
        acc[0] += a.x; acc[1] += a.y; acc[2] += a.z; acc[3] += a.w;
        acc[4] += b.x; acc[5] += b.y; acc[6] += b.z; acc[7] += b.w;
    }
    const float4* zc = (const float4*)(z + (size_t)c * CH + lane * 8);
    float4 za = zc[0], zb = zc[1];
    float zv[8] = {za.x, za.y, za.z, za.w, zb.x, zb.y, zb.z, zb.w};
    float f = fil[c], dv = dinv[c];
    float* yo = Y + (size_t)c * CH + lane * 8;
    float dot = 0.f;
#pragma unroll
    for (int q = 0; q < 8; q++) {
        float v = dv * (acc[q] + f * zv[q]) + bias[lane * 8 + q];
        if (relu) v = fmaxf(v, 0.f);
        yo[q] = v;
        if (p) dot += v * p[lane * 8 + q];
        if (mpart) mp[wid][lane * 8 + q] = v;
    }
    if (p) {
#pragma unroll
        for (int o = 16; o; o >>= 1) dot += __shfl_down_sync(0xffffffffu, dot, o);
        if (lane == 0) scout[c] = dot;
    }
    if (mpart) {
        __syncthreads();
        float s = 0.f;
#pragma unroll
        for (int w = 0; w < 8; w++) s += mp[w][threadIdx.x];
        mpart[(size_t)blockIdx.x * 256 + threadIdx.x] = s;
    }
}

// sparse (A+I)^2 restricted to kept rows/cols (global atomics; A1f pre-zeroed)
__global__ void sparse_augment(const int* __restrict__ pm, const int* __restrict__ colmap,
                               const int* __restrict__ rp, const int* __restrict__ ci,
                               float* __restrict__ A1f, int k) {
    int i = blockIdx.x;
    int pi = pm[i];
    int warp = threadIdx.x >> 5, lane = threadIdx.x & 31;
    float* row = A1f + (size_t)i * k;
    int b0 = rp[pi], b1 = rp[pi + 1];
    for (int e = b0 + threadIdx.x; e < b1; e += 256) {
        int j = colmap[ci[e]];
        if (j >= 0) atomicAdd(row + j, 2.f);
    }
    for (int e1 = b0 + warp; e1 < b1; e1 += 8) {
        int c = ci[e1];
        int c0 = rp[c], c1 = rp[c + 1];
        for (int e2 = c0 + lane; e2 < c1; e2 += 32) {
            int j = colmap[ci[e2]];
            if (j >= 0) atomicAdd(row + j, 1.f);
        }
    }
}

__global__ void finalize_A1(const float* __restrict__ Af, bf16* __restrict__ A,
                            bf16* __restrict__ AT, float* __restrict__ deg, int k) {
    __shared__ float t[64][65];
    int bx = blockIdx.x * 64, by = blockIdx.y * 64;
    int tid = threadIdx.x;
#pragma unroll
    for (int q = 0; q < 16; q++) {
        int s = q * 256 + tid;
        int r = s >> 6, c = s & 63;
        float v = Af[(size_t)(by + r) * k + bx + c];
        if (by + r == bx + c) v = 0.f;
        A[(size_t)(by + r) * k + bx + c] = __float2bfloat16(v);
        t[r][c] = v;
    }
    __syncthreads();
#pragma unroll
    for (int q = 0; q < 16; q++) {
        int s = q * 256 + tid;
        int r = s >> 6, c = s & 63;
        AT[(size_t)(bx + r) * k + by + c] = __float2bfloat16(t[c][r]);
    }
    if (tid < 64) {
        float s = 0.f;
#pragma unroll
        for (int r = 0; r < 64; r++) s += t[r][tid];
        atomicAdd(deg + bx + tid, s);
    }
}

// sum 4 split-K slices + 2*Aprev[pm[r],pm[c]], zero diag, colsum, emit A + AT
__global__ void finalize_aug(const float* __restrict__ Af, const bf16* __restrict__ Aprev,
                             const int* __restrict__ pm, int k, int nprev,
                             bf16* __restrict__ A, bf16* __restrict__ AT,
                             float* __restrict__ deg) {
    __shared__ float t[64][65];
    __shared__ int pmc[64], pmr[64];
    int bx = blockIdx.x * 64, by = blockIdx.y * 64;
    int tid = threadIdx.x;
    if (tid < 64) pmc[tid] = pm[bx + tid];
    else if (tid < 128) pmr[tid - 64] = pm[by + tid - 64];
    __syncthreads();
    size_t kk = (size_t)k * k;
#pragma unroll
    for (int q = 0; q < 16; q++) {
        int s = q * 256 + tid;
        int r = s >> 6, c = s & 63;
        size_t off = (size_t)(by + r) * k + bx + c;
        float v = Af[off] + Af[kk + off] + Af[2 * kk + off] + Af[3 * kk + off] +
                  2.f * __bfloat162float(Aprev[(size_t)pmr[r] * nprev + pmc[c]]);
        if (by + r == bx + c) v = 0.f;
        A[off] = __float2bfloat16(v);
        t[r][c] = v;
    }
    __syncthreads();
#pragma unroll
    for (int q = 0; q < 16; q++) {
        int s = q * 256 + tid;
        int r = s >> 6, c = s & 63;
        AT[(size_t)(bx + r) * k + by + c] = __float2bfloat16(t[c][r]);
    }
    if (tid < 64) {
        float s = 0.f;
#pragma unroll
        for (int r = 0; r < 64; r++) s += t[r][tid];
        atomicAdd(deg + bx + tid, s);
    }
}

// ---------------- single-block BYTE-RADIX top-k select ----------------
template <int SZ>
__global__ void topk_select(const float* __restrict__ s0, int k,
                            int* __restrict__ perm, int* __restrict__ colmap) {
    constexpr int PT = SZ / 1024;
    __shared__ uint32_t key[SZ];
    __shared__ int hist[256];
    __shared__ int wred[33];
    __shared__ uint32_t sh_theta;
    __shared__ int sh_need;
    int tid = threadIdx.x;
    int lane = tid & 31, w = tid >> 5;
#pragma unroll
    for (int q = 0; q < PT; q++) {
        int t = tid * PT + q;
        uint32_t b = __float_as_uint(s0[t]);
        key[t] = (b & 0x80000000u) ? ~b : (b | 0x80000000u);
    }
    if (tid == 0) { sh_theta = 0; sh_need = k; }
    __syncthreads();

    for (int round = 0; round < 4; round++) {
        int shift = 24 - 8 * round;
        uint32_t theta = sh_theta;
        int need = sh_need;
        uint32_t hi_mask = (round == 0) ? 0u : (0xFFFFFFFFu << (shift + 8));
        if (tid < 256) hist[tid] = 0;
        __syncthreads();
#pragma unroll
        for (int q = 0; q < PT; q++) {
            uint32_t kv = key[tid * PT + q];
            if (((kv ^ theta) & hi_mask) == 0)
                atomicAdd(&hist[(kv >> shift) & 255], 1);
        }
        __syncthreads();
        if (tid < 32) {
            int base = tid * 8;
            int v[8], suf[8];
            int run = 0;
#pragma unroll
            for (int j = 7; j >= 0; j--) {
                v[j] = hist[base + j];
                run += v[j];
                suf[j] = run;
            }
            int acc = run;
#pragma unroll
            for (int o = 1; o < 32; o <<= 1) {
                int x = __shfl_down_sync(0xffffffffu, acc, o);
                if (tid + o < 32) acc += x;
            }
            int excl = acc - run;  // totals in lanes > tid
#pragma unroll
            for (int j = 0; j < 8; j++) {
                int gt = excl + suf[j] - v[j];
                if (gt < need && gt + v[j] >= need) {
                    sh_theta = theta | ((uint32_t)(base + j) << shift);
                    sh_need = need - gt;
                }
            }
        }
        __syncthreads();
    }
    const uint32_t theta = sh_theta;
    const int need_eq = sh_need;

    // index-ordered compaction with hierarchical warp scan on packed counters
    int sloc = 0;
#pragma unroll
    for (int q = 0; q < PT; q++) {
        uint32_t kv = key[tid * PT + q];
        sloc += (kv > theta) ? 1 : ((kv == theta) ? 65536 : 0);
    }
    int inc = sloc;
#pragma unroll
    for (int o = 1; o < 32; o <<= 1) {
        int x = __shfl_up_sync(0xffffffffu, inc, o);
        if (lane >= o) inc += x;
    }
    if (lane == 31) wred[w] = inc;
    __syncthreads();
    if (w == 0) {
        int ws = wred[lane];
        int winc = ws;
#pragma unroll
        for (int o = 1; o < 32; o <<= 1) {
            int x = __shfl_up_sync(0xffffffffu, winc, o);
            if (lane >= o) winc += x;
        }
        wred[lane] = winc - ws;
    }
    __syncthreads();
    int pref = wred[w] + inc - sloc;
    int gtp = pref & 0xffff, eqp = pref >> 16;
#pragma unroll
    for (int q = 0; q < PT; q++) {
        int i = tid * PT + q;
        uint32_t kv = key[i];
        bool gt = kv > theta;
        bool eq = (kv == theta);
        bool sel = gt || (eq && eqp < need_eq);
        if (sel) {
            int pos = gtp + (eqp < need_eq ? eqp : need_eq);
            perm[pos] = i;
            colmap[i] = pos;
        }
        gtp += gt;
        eqp += eq;
    }
}

__global__ void mean_final(const float* __restrict__ part, float* __restrict__ out) {
    int j = threadIdx.x;
    float s = 0.f;
    for (int b = 0; b < 512; b++) s += part[(size_t)b * 256 + j];
    out[j] = s / (float)N0;
}

// GCN final reduce over split-K partials + optional fused FULL score.
__global__ void reduce_gcn(const float* __restrict__ part, int S, int partStride, int M,
                           const bf16* __restrict__ zh, const bf16* __restrict__ zl,
                           const float* __restrict__ deg,
                           const float* __restrict__ bias, float* __restrict__ Y, int relu,
                           const float* __restrict__ p, float* __restrict__ scout) {
    int m = blockIdx.x, c = threadIdx.x;
    size_t idx = (size_t)m * 256 + c;
    float s = 0.f;
    for (int q = 0; q < S; q++) s += part[(size_t)q * partStride + idx];
    float z = __bfloat162float(zh[(size_t)c * M + m]) + __bfloat162float(zl[(size_t)c * M + m]);
    float dv = rsqrtf(deg[m] + 2.f);
    float v = dv * (s + 2.f * z) + bias[c];
    if (relu) v = fmaxf(v, 0.f);
    Y[idx] = v;
    if (p) {
        __shared__ float red[8];
        float d = v * p[c];
#pragma unroll
        for (int o = 16; o; o >>= 1) d += __shfl_down_sync(0xffffffffu, d, o);
        if ((c & 31) == 0) red[c >> 5] = d;
        __syncthreads();
        if (c < 8) {
            float a = red[c];
#pragma unroll
            for (int o = 4; o; o >>= 1) a += __shfl_down_sync(0xffu, a, o);
            if (c == 0) scout[m] = a;
        }
    }
}

// ---------------- shared tile loader (bf16, cp.async) ----------------
template <int G>
__device__ __forceinline__ void ld_tile(const bf16* __restrict__ src, int ld,
                                        int row0, int k0, uint16_t* dst, int tid,
                                        const int* __restrict__ pm) {
#pragma unroll
    for (int i = 0; i < 2; i++) {
        int s = tid + i * 256;
        int r = s >> 2, c8 = (s & 3) * 8;
        int row = row0 + r;
        if (G) row = pm[row];
        const bf16* g = src + (size_t)row * ld + k0 + c8;
        uint32_t sm = (uint32_t)__cvta_generic_to_shared(dst + r * 40 + c8);
        asm volatile("cp.async.ca.shared.global [%0], [%1], 16;\n" ::"r"(sm), "l"(g));
    }
}

// ---------------- MMA compute helper ----------------
__device__ __forceinline__ void mma_block(const uint16_t* Asb, const uint16_t* Bsb,
                                          int ks, int g, int tg, int wm, int wn,
                                          float acc[4][4][4]) {
    uint32_t af[4][4], bfr[4][2];
    const int kc = ks + 2 * tg;
#pragma unroll
    for (int mf = 0; mf < 4; mf++) {
        int m = wm * 64 + mf * 16 + g;
        af[mf][0] = *(const uint32_t*)&Asb[m * 40 + kc];
        af[mf][1] = *(const uint32_t*)&Asb[(m + 8) * 40 + kc];
        af[mf][2] = *(const uint32_t*)&Asb[m * 40 + kc + 8];
        af[mf][3] = *(const uint32_t*)&Asb[(m + 8) * 40 + kc + 8];
    }
#pragma unroll
    for (int nf = 0; nf < 4; nf++) {
        int n = wn * 32 + nf * 8 + g;
        bfr[nf][0] = *(const uint32_t*)&Bsb[n * 40 + kc];
        bfr[nf][1] = *(const uint32_t*)&Bsb[n * 40 + kc + 8];
    }
#pragma unroll
    for (int mf = 0; mf < 4; mf++)
#pragma unroll
        for (int nf = 0; nf < 4; nf++)
            asm volatile(
                "mma.sync.aligned.m16n8k16.row.col.f32.bf16.bf16.f32 "
                "{%0,%1,%2,%3},{%4,%5,%6,%7},{%8,%9},{%0,%1,%2,%3};"
                : "+f"(acc[mf][nf][0]), "+f"(acc[mf][nf][1]),
                  "+f"(acc[mf][nf][2]), "+f"(acc[mf][nf][3])
                : "r"(af[mf][0]), "r"(af[mf][1]), "r"(af[mf][2]),
                  "r"(af[mf][3]), "r"(bfr[nf][0]), "r"(bfr[nf][1]));
}

// ---------------- bf16-operand GEMM, 3-STAGE pipeline ----------------
template <int NPROD, int G>
__global__ void __launch_bounds__(256, 2) mma_gemm(
    const bf16* __restrict__ A0p, int lda,
    const bf16* __restrict__ B0p, const bf16* __restrict__ B1p, int ldb,
    float* __restrict__ Cp, int ldc, int ksplit, size_t partStride,
    const int* __restrict__ pm) {
    constexpr int PB = (NPROD >= 2) ? 2 : 1;
    constexpr int TS = 128 * 40;            // u16 per tile
    constexpr int SS = (1 + PB) * TS;       // u16 per stage
    extern __shared__ __align__(16) uint16_t sh[];

    const int tid = threadIdx.x;
    const int lane = tid & 31, warp = tid >> 5;
    const int g = lane >> 2, tg = lane & 3;
    const int wm = warp >> 2, wn = warp & 3;
    const int m0 = blockIdx.y * 128, j0 = blockIdx.x * 128;

    float acc[4][4][4];
#pragma unroll
    for (int a = 0; a < 4; a++)
#pragma unroll
        for (int b = 0; b < 4; b++)
#pragma unroll
            for (int e = 0; e < 4; e++) acc[a][b][e] = 0.f;

    auto load_stage = [&](int st, int k0) {
        ld_tile<G>(A0p, lda, m0, k0, sh + st * SS, tid, pm);
        ld_tile<G>(B0p, ldb, j0, k0, sh + st * SS + TS, tid, pm);
        if (PB == 2) ld_tile<G>(B1p, ldb, j0, k0, sh + st * SS + 2 * TS, tid, pm);
        asm volatile("cp.async.commit_group;\n" ::);
    };

    const int kb = blockIdx.z * ksplit;
    const int nt = ksplit / 32;

    load_stage(0, kb);
    if (nt > 1) load_stage(1, kb + 32);
    int st = 0;
    for (int it = 0; it < nt; it++) {
        if (it + 1 < nt)
            asm volatile("cp.async.wait_group 1;\n" ::);
        else
            asm volatile("cp.async.wait_group 0;\n" ::);
        __syncthreads();  // stage st ready; compute(it-1) readers done
        if (it + 2 < nt) load_stage((st + 2) % 3, kb + (it + 2) * 32);
        const uint16_t* As = sh + st * SS;
        const uint16_t* Bs0 = As + TS;
#pragma unroll
        for (int ks = 0; ks < 32; ks += 16)
            mma_block(As, Bs0, ks, g, tg, wm, wn, acc);
        if (PB == 2) {
            const uint16_t* Bs1 = As + 2 * TS;
#pragma unroll
            for (int ks = 0; ks < 32; ks += 16)
                mma_block(As, Bs1, ks, g, tg, wm, wn, acc);
        }
        st = (st + 1) % 3;
    }

#pragma unroll
    for (int mf = 0; mf < 4; mf++)
#pragma unroll
        for (int nf = 0; nf < 4; nf++)
#pragma unroll
            for (int e = 0; e < 4; e++) {
                int m = m0 + wm * 64 + mf * 16 + g + (e >> 1) * 8;
                int c = j0 + wn * 32 + nf * 8 + 2 * tg + (e & 1);
                Cp[(size_t)blockIdx.z * partStride + (size_t)m * ldc + c] = acc[mf][nf][e];
            }
}

// ---------------- fused XW GEMM (proven pipeline) ----------------
// IN=1: A = Xsrc[m][k]
// IN=2: A = Xsrc[idx[m]][k] * tanh(s[idx[m]]*pn)
// IN=3: A = Xsrc[m][k] + (idx[m]>=0 ? xcur[idx[m]][k] : 0)
// MODE=1: z = rsqrt(scl[m]+2)*acc -> zhi/zlo transposed [c*n+m]
// MODE=2: z = scl[m]*acc -> fp32 [m*256+c]
template <int MODE, int IN>
__global__ void __launch_bounds__(256, 2) xw_gemm(
    const float* __restrict__ Xsrc, int K,
    const float* __restrict__ xcur, const int* __restrict__ idx,
    const float* __restrict__ s, const float* __restrict__ pn,
    const bf16* __restrict__ Bh, const bf16* __restrict__ Bl,
    void* __restrict__ Cp, void* __restrict__ C2p, int n,
    const float* __restrict__ scl) {
    extern __shared__ __align__(16) uint16_t sh[];
    uint16_t* Ahi = sh;
    uint16_t* Alo = sh + 5120;
    uint16_t* Bst = sh + 2 * 5120;

    const int tid = threadIdx.x;
    const int lane = tid & 31, warp = tid >> 5;
    const int g = lane >> 2, tg = lane & 3;
    const int wm = warp >> 2, wn = warp & 3;
    const int m0 = blockIdx.y * 128, j0 = blockIdx.x * 128;

    float acc[4][4][4];
#pragma unroll
    for (int a = 0; a < 4; a++)
#pragma unroll
        for (int b = 0; b < 4; b++)
#pragma unroll
            for (int e = 0; e < 4; e++) acc[a][b][e] = 0.f;

    auto loadB = [&](int st, int k0) {
        ld_tile<0>(Bh, K, j0, k0, Bst + st * 2 * 5120, tid, nullptr);
        ld_tile<0>(Bl, K, j0, k0, Bst + (st * 2 + 1) * 5120, tid, nullptr);
        asm volatile("cp.async.commit_group;\n" ::);
    };

    const int arow = tid >> 1;
    const int coff = (tid & 1) * 16;
    const int m = m0 + arow;
    int srow = 0;
    float gate = 1.f;
    if (IN == 2) {
        srow = idx[m];
        gate = tanhf(s[srow] * pn[0]);
    } else if (IN == 3) {
        srow = idx[m];
    }

    const int nt = K / 32;
    loadB(0, 0);
    for (int it = 0; it < nt; it++) {
        float av[16];
        int kb = it * 32 + coff;
        if (IN == 1) {
#pragma unroll
            for (int q = 0; q < 4; q++) {
                float4 v = *(const float4*)(Xsrc + (size_t)m * K + kb + q * 4);
                av[q * 4] = v.x; av[q * 4 + 1] = v.y; av[q * 4 + 2] = v.z; av[q * 4 + 3] = v.w;
            }
        } else if (IN == 2) {
#pragma unroll
            for (int q = 0; q < 4; q++) {
                float4 v = *(const float4*)(Xsrc + (size_t)srow * K + kb + q * 4);
                av[q * 4] = v.x * gate; av[q * 4 + 1] = v.y * gate;
                av[q * 4 + 2] = v.z * gate; av[q * 4 + 3] = v.w * gate;
            }
        } else {
#pragma unroll
            for (int q = 0; q < 4; q++) {
                float4 v = *(const float4*)(Xsrc + (size_t)m * K + kb + q * 4);
                av[q * 4] = v.x; av[q * 4 + 1] = v.y; av[q * 4 + 2] = v.z; av[q * 4 + 3] = v.w;
            }
            if (srow >= 0) {
#pragma unroll
                for (int q = 0; q < 4; q++) {
                    float4 v = *(const float4*)(xcur + (size_t)srow * K + kb + q * 4);
                    av[q * 4] += v.x; av[q * 4 + 1] += v.y;
                    av[q * 4 + 2] += v.z; av[q * 4 + 3] += v.w;
                }
            }
        }
        if (it + 1 < nt) {
            loadB((it + 1) & 1, (it + 1) * 32);
            asm volatile("cp.async.wait_group 1;\n" ::);
        } else {
            asm volatile("cp.async.wait_group 0;\n" ::);
        }
        __syncthreads();  // prev compute done -> Ahi writable; B stage visible
#pragma unroll
        for (int e = 0; e < 16; e++) {
            float v = av[e];
            bf16 h = __float2bfloat16(v);
            Ahi[arow * 40 + coff + e] = __bfloat16_as_ushort(h);
            Alo[arow * 40 + coff + e] =
                __bfloat16_as_ushort(__float2bfloat16(v - __bfloat162float(h)));
        }
        __syncthreads();
        const uint16_t* Bhi_s = Bst + (it & 1) * 2 * 5120;
        const uint16_t* Blo_s = Bhi_s + 5120;
#pragma unroll
        for (int ks = 0; ks < 32; ks += 16) {
            mma_block(Ahi, Bhi_s, ks, g, tg, wm, wn, acc);
            mma_block(Ahi, Blo_s, ks, g, tg, wm, wn, acc);
            mma_block(Alo, Bhi_s, ks, g, tg, wm, wn, acc);
        }
    }

#pragma unroll
    for (int mf = 0; mf < 4; mf++)
#pragma unroll
        for (int nf = 0; nf < 4; nf++)
#pragma unroll
            for (int e = 0; e < 4; e++) {
                int mm = m0 + wm * 64 + mf * 16 + g + (e >> 1) * 8;
                int c = j0 + wn * 32 + nf * 8 + 2 * tg + (e & 1);
                float v = acc[mf][nf][e];
                if (MODE == 1) {
                    v *= rsqrtf(scl[mm] + 2.f);
                    bf16 h = __float2bfloat16(v);
                    ((bf16*)Cp)[(size_t)c * n + mm] = h;
                    ((bf16*)C2p)[(size_t)c * n + mm] =
                        __float2bfloat16(v - __bfloat162float(h));
                } else {
                    ((float*)Cp)[(size_t)mm * 256 + c] = v * scl[mm];
                }
            }
}

// ---------------- host orchestration ----------------
#define SYM(p, s)                     \
    do {                              \
        void* _t = nullptr;           \
        cudaGetSymbolAddress(&_t, s); \
        p = (decltype(p))_t;          \
    } while (0)

extern "C" void kernel_launch(void* const* d_in, const int* in_sizes, int n_in,
                              void* d_out, int out_size) {
    const float* x_in = (const float*)d_in[0];
    const int* ei     = (const int*)d_in[1];
    const float* w_d0 = (const float*)d_in[3];
    const float* b_d0 = (const float*)d_in[4];
    const float* w_d  = (const float*)d_in[5];
    const float* b_d  = (const float*)d_in[6];
    const float* p_at = (const float*)d_in[7];
    const float* w_u  = (const float*)d_in[8];
    const float* b_u  = (const float*)d_in[9];
    float* out = (float*)d_out;
    const int E = in_sizes[1] / 2;

    bf16 *A1, *A2, *A3, *AT1, *AT2, *AT3, *WH, *WL, *zhi, *zlo;
    float *X0, *X1, *X2, *Xc, *Cpart, *zf, *A1f, *dinv0, *fil0, *sc, *pns, *mpart;
    int *zblk, *perm, *colmap, *rpi, *rpo, *cii, *cio, *curi, *curo;
    SYM(A1, g_A1);   SYM(A2, g_A2);   SYM(A3, g_A3);
    SYM(AT1, g_AT1); SYM(AT2, g_AT2); SYM(AT3, g_AT3);
    SYM(WH, g_WH);   SYM(WL, g_WL);
    SYM(zhi, g_zhi); SYM(zlo, g_zlo);
    SYM(X0, g_X0);   SYM(X1, g_X1);   SYM(X2, g_X2);
    SYM(Xc, g_Xc);   SYM(Cpart, g_Cpart);
    SYM(zf, g_z);    SYM(A1f, g_A1f);
    SYM(zblk, g_zblk);
    SYM(dinv0, g_dinv0); SYM(fil0, g_fil0);
    SYM(sc, g_s);    SYM(pns, g_pns); SYM(mpart, g_mpart);
    SYM(perm, g_perm); SYM(colmap, g_colmap);
    SYM(rpi, g_rpi); SYM(rpo, g_rpo); SYM(cii, g_cii); SYM(cio, g_cio);
    SYM(curi, g_curi); SYM(curo, g_curo);
    int* cnt = zblk;
    float* deg = (float*)(zblk + 3 * N0);

    cudaFuncSetAttribute(mma_gemm<2, 0>, cudaFuncAttributeMaxDynamicSharedMemorySize, 92160);
    cudaFuncSetAttribute(mma_gemm<1, 1>, cudaFuncAttributeMaxDynamicSharedMemorySize, 61440);
    cudaFuncSetAttribute(xw_gemm<2, 1>, cudaFuncAttributeMaxDynamicSharedMemorySize, 61440);
    cudaFuncSetAttribute(xw_gemm<2, 3>, cudaFuncAttributeMaxDynamicSharedMemorySize, 61440);
    cudaFuncSetAttribute(xw_gemm<1, 2>, cudaFuncAttributeMaxDynamicSharedMemorySize, 61440);
    cudaFuncSetAttribute(xw_gemm<1, 3>, cudaFuncAttributeMaxDynamicSharedMemorySize, 61440);

    bf16* Alv[4] = {nullptr, A1, A2, A3};
    bf16* ATlv[4] = {nullptr, AT1, AT2, AT3};
    float* Xs[3] = {X0, X1, X2};
    const int ns[4] = {4096, 2048, 1024, 512};

    // ---- fused setup (weight split + zeroing + colmap) ----
    setup_all<<<cdiv(NWSPLIT + 10 * N0, 256), 256>>>(w_d0, w_d, w_u, WH, WL, zblk, colmap);
    count_deg<<<cdiv(E, 256), 256>>>(ei, E, cnt);
    scan_build<<<1, 1024>>>(cnt, rpi, rpo, curi, curo, dinv0, fil0, p_at, pns);
    fill_csr<<<cdiv(E, 256), 256>>>(ei, E, curi, curo, cii, cio);

    // dense GCN levels 1..3 (full score fused into reduce when pnext)
    auto gcn = [&](int lvl, int slot, const float* Xsrc, const int* pidx, int IN,
                   const float* bias, float* Y, int relu, const float* pnext) {
        int n = ns[lvl];
        if (IN == 2)
            xw_gemm<1, 2><<<dim3(2, n / 128), 256, 61440>>>(
                Xsrc, 256, nullptr, pidx, sc, pns + (lvl - 1), WH + slot * 65536,
                WL + slot * 65536, zhi, zlo, n, deg + lvl * N0);
        else
            xw_gemm<1, 3><<<dim3(2, n / 128), 256, 61440>>>(
                Xsrc, 256, Xc, pidx, nullptr, nullptr, WH + slot * 65536,
                WL + slot * 65536, zhi, zlo, n, deg + lvl * N0);
        mma_gemm<2, 0><<<dim3(2, n / 128, 8), 256, 92160>>>(
            ATlv[lvl], n, zhi, zlo, n, Cpart, 256, n / 8, (size_t)n * 256, nullptr);
        reduce_gcn<<<n, 256>>>(Cpart, 8, n * 256, n, zhi, zlo, deg + lvl * N0,
                               bias, Y, relu, pnext, sc);
    };

    // ---- level-0 down GCN (score fused into spmv) ----
    xw_gemm<2, 1><<<dim3(2, N0 / 128), 256, 61440>>>(
        x_in, 128, nullptr, nullptr, nullptr, nullptr, WH, WL, zf, nullptr, N0, dinv0);
    spmv_gcn<<<N0 / 8, 256>>>(rpi, cii, zf, dinv0, fil0, b_d0, X0, 1, p_at, sc, nullptr);

    // ---- down path ----
    for (int i = 0; i < 3; i++) {
        int n = ns[i], k = ns[i + 1];
        int* pm = perm + i * 2048;
        int* cm = colmap + i * N0;

        if (i == 0) topk_select<4096><<<1, 1024>>>(sc, k, pm, cm);
        else if (i == 1) topk_select<2048><<<1, 1024>>>(sc, k, pm, cm);
        else topk_select<1024><<<1, 1024>>>(sc, k, pm, cm);

        if (i == 0) {
            cudaMemsetAsync(A1f, 0, (size_t)k * k * sizeof(float));
            sparse_augment<<<k, 256>>>(pm, cm, rpo, cio, A1f, k);
            finalize_A1<<<dim3(k / 64, k / 64), 256>>>(A1f, A1, AT1, deg + N0, k);
        } else {
            mma_gemm<1, 1><<<dim3(k / 128, k / 128, 4), 256, 61440>>>(
                Alv[i], n, ATlv[i], nullptr, n, A1f, k, n / 4, (size_t)k * k, pm);
            finalize_aug<<<dim3(k / 64, k / 64), 256>>>(A1f, Alv[i], pm, k, n,
                                                        Alv[i + 1], ATlv[i + 1],
                                                        deg + (i + 1) * N0);
        }

        float* Y = (i < 2) ? Xs[i + 1] : Xc;
        const float* pnext = (i < 2) ? (p_at + (i + 1) * CH) : nullptr;
        gcn(i + 1, 1 + i, Xs[i], pm, 2, b_d + i * CH, Y, 1, pnext);
    }

    // ---- up path ----
    for (int i = 0; i < 3; i++) {
        int j = 2 - i;
        if (j == 0) {
            xw_gemm<2, 3><<<dim3(2, N0 / 128), 256, 61440>>>(
                X0, 256, Xc, colmap, nullptr, nullptr,
                WH + (4 + i) * 65536, WL + (4 + i) * 65536, zf, nullptr, N0, dinv0);
            // final GCN: fuse deterministic mean partials
            spmv_gcn<<<N0 / 8, 256>>>(rpi, cii, zf, dinv0, fil0, b_u + i * CH, Xc, 0,
                                      nullptr, nullptr, mpart);
        } else {
            gcn(j, 4 + i, Xs[j], colmap + j * N0, 3, b_u + i * CH, Xc, 1, nullptr);
        }
    }

    mean_final<<<1, 256>>>(mpart, out);
}

// round 17
// speedup vs baseline: 1.0794x; 1.0027x over previous
#include <cuda_runtime.h>
#include <cuda_bf16.h>
#include <math.h>
#include <stdint.h>

#define N0 4096
#define CH 256
#define EMAX 131072

using bf16 = __nv_bfloat16;

// ---------------- scratch ----------------
__device__ bf16  g_A1[2048 * 2048];
__device__ bf16  g_A2[1024 * 1024];
__device__ bf16  g_A3[512 * 512];
__device__ bf16  g_AT1[2048 * 2048];
__device__ bf16  g_AT2[1024 * 1024];
__device__ bf16  g_AT3[512 * 512];
__device__ float g_A1f[2048 * 2048];   // augment split-K slices
__device__ float g_X0[N0 * CH];
__device__ float g_X1[2048 * CH];
__device__ float g_X2[1024 * CH];
__device__ float g_Xc[N0 * CH];
__device__ float g_z[N0 * CH];
__device__ bf16  g_WH[7 * 65536];
__device__ bf16  g_WL[7 * 65536];
__device__ bf16  g_zhi[CH * N0];
__device__ bf16  g_zlo[CH * N0];
__device__ float g_Cpart[8 * 2048 * CH];
__device__ int   g_zblk[7 * N0];       // [cnt: 3*N0 | deg: 4*N0(as float)]
__device__ float g_dinv0[N0];
__device__ float g_fil0[N0];
__device__ float g_s[N0];
__device__ float g_pns[3];
__device__ int   g_perm[3][2048];
__device__ int   g_colmap[3][N0];
__device__ int g_rpi[N0 + 1], g_rpo[N0 + 1];
__device__ int g_cii[EMAX], g_cio[EMAX];
__device__ int g_curi[N0], g_curo[N0];
__device__ float g_mpart[512 * 256];

static inline int cdiv(int a, int b) { return (a + b - 1) / b; }

#define NWSPLIT (32768 + 6 * 65536)  // 425984 weight elements

// ---------------- fused setup: weight split + zblk zero + colmap fill ----------------
__global__ void setup_all(const float* __restrict__ w_d0, const float* __restrict__ w_d,
                          const float* __restrict__ w_u, bf16* __restrict__ hi,
                          bf16* __restrict__ lo, int* __restrict__ zblk,
                          int* __restrict__ colmap) {
    int idx = blockIdx.x * blockDim.x + threadIdx.x;
    if (idx < NWSPLIT) {
        float v;
        int o;
        if (idx < 32768) {
            int k = idx >> 8, c = idx & 255;
            v = w_d0[idx];
            o = c * 128 + k;
        } else {
            int t = idx - 32768;
            int mat = t >> 16, e = t & 65535;
            int k = e >> 8, c = e & 255;
            v = (mat < 3) ? w_d[mat * 65536 + e] : w_u[(mat - 3) * 65536 + e];
            o = (1 + mat) * 65536 + c * 256 + k;
        }
        bf16 h = __float2bfloat16(v);
        hi[o] = h;
        lo[o] = __float2bfloat16(v - __bfloat162float(h));
    } else if (idx < NWSPLIT + 7 * N0) {
        zblk[idx - NWSPLIT] = 0;
    } else if (idx < NWSPLIT + 7 * N0 + 3 * N0) {
        colmap[idx - NWSPLIT - 7 * N0] = -1;
    }
}

// ---------------- CSR build ----------------
__global__ void count_deg(const int* __restrict__ ei, int E, int* __restrict__ cnt) {
    int i = blockIdx.x * blockDim.x + threadIdx.x;
    if (i >= E) return;
    int s = ei[i], d = ei[E + i];
    atomicAdd(cnt + N0 + s, 1);
    atomicAdd(cnt + d, 1);
    if (s == d) atomicAdd(cnt + 2 * N0 + s, 1);
}

// hierarchical warp-shfl scan (3 syncs); wsum needs 33 ints
__device__ void scan4096(const int* __restrict__ cnt, int* __restrict__ rp,
                         int* __restrict__ cur, int* wsum) {
    int t = threadIdx.x, lane = t & 31, w = t >> 5;
    int base = t * 4;
    int v0 = cnt[base], v1 = cnt[base + 1], v2 = cnt[base + 2], v3 = cnt[base + 3];
    int s01 = v0 + v1;
    int s = s01 + v2 + v3;
    int inc = s;
#pragma unroll
    for (int o = 1; o < 32; o <<= 1) {
        int x = __shfl_up_sync(0xffffffffu, inc, o);
        if (lane >= o) inc += x;
    }
    if (lane == 31) wsum[w] = inc;
    __syncthreads();
    if (w == 0) {
        int ws = wsum[lane];
        int winc = ws;
#pragma unroll
        for (int o = 1; o < 32; o <<= 1) {
            int x = __shfl_up_sync(0xffffffffu, winc, o);
            if (lane >= o) winc += x;
        }
        if (lane == 31) wsum[32] = winc;
        wsum[lane] = winc - ws;  // exclusive per-warp offset
    }
    __syncthreads();
    int excl = wsum[w] + inc - s;
    rp[base] = excl;           cur[base] = excl;
    rp[base + 1] = excl + v0;  cur[base + 1] = excl + v0;
    rp[base + 2] = excl + s01; cur[base + 2] = excl + s01;
    rp[base + 3] = excl + s01 + v2; cur[base + 3] = excl + s01 + v2;
    if (t == 1023) rp[4096] = wsum[32];
    __syncthreads();
}

__global__ void scan_build(const int* __restrict__ cnt,
                           int* rpi, int* rpo, int* curi, int* curo,
                           float* __restrict__ dinv, float* __restrict__ fil,
                           const float* __restrict__ p_at, float* __restrict__ pns) {
    __shared__ int wsum[33];
    scan4096(cnt, rpi, curi, wsum);
    scan4096(cnt + N0, rpo, curo, wsum);
    int t = threadIdx.x;
#pragma unroll
    for (int q = 0; q < 4; q++) {
        int c = t * 4 + q;
        float f = (cnt[2 * N0 + c] == 0) ? 2.f : 0.f;
        fil[c] = f;
        dinv[c] = rsqrtf((float)cnt[c] + f);
    }
    if (t < 96) {
        int w = t >> 5, lane = t & 31;
        float a = 0.f;
#pragma unroll
        for (int q = 0; q < 8; q++) {
            float v = p_at[w * 256 + lane + 32 * q];
            a += v * v;
        }
#pragma unroll
        for (int o = 16; o; o >>= 1) a += __shfl_down_sync(0xffffffffu, a, o);
        if (lane == 0) pns[w] = rsqrtf(a);
    }
}

__global__ void fill_csr(const int* __restrict__ ei, int E, int* curi, int* curo,
                         int* __restrict__ cii, int* __restrict__ cio) {
    int i = blockIdx.x * blockDim.x + threadIdx.x;
    if (i >= E) return;
    int s = ei[i], d = ei[E + i];
    int po = atomicAdd(curo + s, 1);
    cio[po] = d;
    int pi = atomicAdd(curi + d, 1);
    cii[pi] = s;
}

// sparse GCN + optional fused score (p) + optional fused mean partials (mpart).
__global__ void spmv_gcn(const int* __restrict__ rp, const int* __restrict__ ci,
                         const float* __restrict__ z, const float* __restrict__ dinv,
                         const float* __restrict__ fil, const float* __restrict__ bias,
                         float* __restrict__ Y, int relu,
                         const float* __restrict__ p, float* __restrict__ scout,
                         float* __restrict__ mpart) {
    __shared__ float mp[8][256];
    int wid = threadIdx.x >> 5;
    int c = blockIdx.x * 8 + wid;
    int lane = threadIdx.x & 31;
    float acc[8] = {0.f, 0.f, 0.f, 0.f, 0.f, 0.f, 0.f, 0.f};
    int e0 = rp[c], e1 = rp[c + 1];
    for (int e = e0; e < e1; e++) {
        int r = ci[e];
        const float4* zp = (const float4*)(z + (size_t)r * CH + lane * 8);
        float4 a = zp[0], b = zp[1];
        acc[0] += a.x; acc[1] += a.y; acc[2] += a.z; acc[3] += a.w;
        acc[4] += b.x; acc[5] += b.y; acc[6] += b.z; acc[7] += b.w;
    }
    const float4* zc = (const float4*)(z + (size_t)c * CH + lane * 8);
    float4 za = zc[0], zb = zc[1];
    float zv[8] = {za.x, za.y, za.z, za.w, zb.x, zb.y, zb.z, zb.w};
    float f = fil[c], dv = dinv[c];
    float* yo = Y + (size_t)c * CH + lane * 8;
    float dot = 0.f;
#pragma unroll
    for (int q = 0; q < 8; q++) {
        float v = dv * (acc[q] + f * zv[q]) + bias[lane * 8 + q];
        if (relu) v = fmaxf(v, 0.f);
        yo[q] = v;
        if (p) dot += v * p[lane * 8 + q];
        if (mpart) mp[wid][lane * 8 + q] = v;
    }
    if (p) {
#pragma unroll
        for (int o = 16; o; o >>= 1) dot += __shfl_down_sync(0xffffffffu, dot, o);
        if (lane == 0) scout[c] = dot;
    }
    if (mpart) {
        __syncthreads();
        float s = 0.f;
#pragma unroll
        for (int w = 0; w < 8; w++) s += mp[w][threadIdx.x];
        mpart[(size_t)blockIdx.x * 256 + threadIdx.x] = s;
    }
}

// smem-staged sparse (A+I)^2 restricted to kept rows/cols; writes FULL fp32 row
// (kills the 16MB A1f memset). One block per output row; purely local sync.
__global__ void sparse_augment(const int* __restrict__ pm, const int* __restrict__ colmap,
                               const int* __restrict__ rp, const int* __restrict__ ci,
                               float* __restrict__ A1f, int k) {
    __shared__ float row[2048];
    int i = blockIdx.x;
    int pi = pm[i];
    int warp = threadIdx.x >> 5, lane = threadIdx.x & 31;
    for (int j = threadIdx.x; j < k; j += 256) row[j] = 0.f;
    __syncthreads();
    int b0 = rp[pi], b1 = rp[pi + 1];
    for (int e = b0 + threadIdx.x; e < b1; e += 256) {
        int j = colmap[ci[e]];
        if (j >= 0) atomicAdd(&row[j], 2.f);
    }
    for (int e1 = b0 + warp; e1 < b1; e1 += 8) {
        int c = ci[e1];
        int c0 = rp[c], c1 = rp[c + 1];
        for (int e2 = c0 + lane; e2 < c1; e2 += 32) {
            int j = colmap[ci[e2]];
            if (j >= 0) atomicAdd(&row[j], 1.f);
        }
    }
    __syncthreads();
    float* out = A1f + (size_t)i * k;
    for (int j = threadIdx.x; j < k; j += 256) out[j] = row[j];
}

__global__ void finalize_A1(const float* __restrict__ Af, bf16* __restrict__ A,
                            bf16* __restrict__ AT, float* __restrict__ deg, int k) {
    __shared__ float t[64][65];
    int bx = blockIdx.x * 64, by = blockIdx.y * 64;
    int tid = threadIdx.x;
#pragma unroll
    for (int q = 0; q < 16; q++) {
        int s = q * 256 + tid;
        int r = s >> 6, c = s & 63;
        float v = Af[(size_t)(by + r) * k + bx + c];
        if (by + r == bx + c) v = 0.f;
        A[(size_t)(by + r) * k + bx + c] = __float2bfloat16(v);
        t[r][c] = v;
    }
    __syncthreads();
#pragma unroll
    for (int q = 0; q < 16; q++) {
        int s = q * 256 + tid;
        int r = s >> 6, c = s & 63;
        AT[(size_t)(bx + r) * k + by + c] = __float2bfloat16(t[c][r]);
    }
    if (tid < 64) {
        float s = 0.f;
#pragma unroll
        for (int r = 0; r < 64; r++) s += t[r][tid];
        atomicAdd(deg + bx + tid, s);
    }
}

// sum 4 split-K slices + 2*Aprev[pm[r],pm[c]], zero diag, colsum, emit A + AT
__global__ void finalize_aug(const float* __restrict__ Af, const bf16* __restrict__ Aprev,
                             const int* __restrict__ pm, int k, int nprev,
                             bf16* __restrict__ A, bf16* __restrict__ AT,
                             float* __restrict__ deg) {
    __shared__ float t[64][65];
    __shared__ int pmc[64], pmr[64];
    int bx = blockIdx.x * 64, by = blockIdx.y * 64;
    int tid = threadIdx.x;
    if (tid < 64) pmc[tid] = pm[bx + tid];
    else if (tid < 128) pmr[tid - 64] = pm[by + tid - 64];
    __syncthreads();
    size_t kk = (size_t)k * k;
#pragma unroll
    for (int q = 0; q < 16; q++) {
        int s = q * 256 + tid;
        int r = s >> 6, c = s & 63;
        size_t off = (size_t)(by + r) * k + bx + c;
        float v = Af[off] + Af[kk + off] + Af[2 * kk + off] + Af[3 * kk + off] +
                  2.f * __bfloat162float(Aprev[(size_t)pmr[r] * nprev + pmc[c]]);
        if (by + r == bx + c) v = 0.f;
        A[off] = __float2bfloat16(v);
        t[r][c] = v;
    }
    __syncthreads();
#pragma unroll
    for (int q = 0; q < 16; q++) {
        int s = q * 256 + tid;
        int r = s >> 6, c = s & 63;
        AT[(size_t)(bx + r) * k + by + c] = __float2bfloat16(t[c][r]);
    }
    if (tid < 64) {
        float s = 0.f;
#pragma unroll
        for (int r = 0; r < 64; r++) s += t[r][tid];
        atomicAdd(deg + bx + tid, s);
    }
}

// ---------------- single-block BYTE-RADIX top-k select ----------------
template <int SZ>
__global__ void topk_select(const float* __restrict__ s0, int k,
                            int* __restrict__ perm, int* __restrict__ colmap) {
    constexpr int PT = SZ / 1024;
    __shared__ uint32_t key[SZ];
    __shared__ int hist[256];
    __shared__ int wred[33];
    __shared__ uint32_t sh_theta;
    __shared__ int sh_need;
    int tid = threadIdx.x;
    int lane = tid & 31, w = tid >> 5;
#pragma unroll
    for (int q = 0; q < PT; q++) {
        int t = tid * PT + q;
        uint32_t b = __float_as_uint(s0[t]);
        key[t] = (b & 0x80000000u) ? ~b : (b | 0x80000000u);
    }
    if (tid == 0) { sh_theta = 0; sh_need = k; }
    __syncthreads();

    for (int round = 0; round < 4; round++) {
        int shift = 24 - 8 * round;
        uint32_t theta = sh_theta;
        int need = sh_need;
        uint32_t hi_mask = (round == 0) ? 0u : (0xFFFFFFFFu << (shift + 8));
        if (tid < 256) hist[tid] = 0;
        __syncthreads();
#pragma unroll
        for (int q = 0; q < PT; q++) {
            uint32_t kv = key[tid * PT + q];
            if (((kv ^ theta) & hi_mask) == 0)
                atomicAdd(&hist[(kv >> shift) & 255], 1);
        }
        __syncthreads();
        if (tid < 32) {
            int base = tid * 8;
            int v[8], suf[8];
            int run = 0;
#pragma unroll
            for (int j = 7; j >= 0; j--) {
                v[j] = hist[base + j];
                run += v[j];
                suf[j] = run;
            }
            int acc = run;
#pragma unroll
            for (int o = 1; o < 32; o <<= 1) {
                int x = __shfl_down_sync(0xffffffffu, acc, o);
                if (tid + o < 32) acc += x;
            }
            int excl = acc - run;  // totals in lanes > tid
#pragma unroll
            for (int j = 0; j < 8; j++) {
                int gt = excl + suf[j] - v[j];
                if (gt < need && gt + v[j] >= need) {
                    sh_theta = theta | ((uint32_t)(base + j) << shift);
                    sh_need = need - gt;
                }
            }
        }
        __syncthreads();
    }
    const uint32_t theta = sh_theta;
    const int need_eq = sh_need;

    int sloc = 0;
#pragma unroll
    for (int q = 0; q < PT; q++) {
        uint32_t kv = key[tid * PT + q];
        sloc += (kv > theta) ? 1 : ((kv == theta) ? 65536 : 0);
    }
    int inc = sloc;
#pragma unroll
    for (int o = 1; o < 32; o <<= 1) {
        int x = __shfl_up_sync(0xffffffffu, inc, o);
        if (lane >= o) inc += x;
    }
    if (lane == 31) wred[w] = inc;
    __syncthreads();
    if (w == 0) {
        int ws = wred[lane];
        int winc = ws;
#pragma unroll
        for (int o = 1; o < 32; o <<= 1) {
            int x = __shfl_up_sync(0xffffffffu, winc, o);
            if (lane >= o) winc += x;
        }
        wred[lane] = winc - ws;
    }
    __syncthreads();
    int pref = wred[w] + inc - sloc;
    int gtp = pref & 0xffff, eqp = pref >> 16;
#pragma unroll
    for (int q = 0; q < PT; q++) {
        int i = tid * PT + q;
        uint32_t kv = key[i];
        bool gt = kv > theta;
        bool eq = (kv == theta);
        bool sel = gt || (eq && eqp < need_eq);
        if (sel) {
            int pos = gtp + (eqp < need_eq ? eqp : need_eq);
            perm[pos] = i;
            colmap[i] = pos;
        }
        gtp += gt;
        eqp += eq;
    }
}

__global__ void mean_final(const float* __restrict__ part, float* __restrict__ out) {
    int j = threadIdx.x;
    float s = 0.f;
    for (int b = 0; b < 512; b++) s += part[(size_t)b * 256 + j];
    out[j] = s / (float)N0;
}

// GCN final reduce over split-K partials + optional fused FULL score.
__global__ void reduce_gcn(const float* __restrict__ part, int S, int partStride, int M,
                           const bf16* __restrict__ zh, const bf16* __restrict__ zl,
                           const float* __restrict__ deg,
                           const float* __restrict__ bias, float* __restrict__ Y, int relu,
                           const float* __restrict__ p, float* __restrict__ scout) {
    int m = blockIdx.x, c = threadIdx.x;
    size_t idx = (size_t)m * 256 + c;
    float s = 0.f;
    for (int q = 0; q < S; q++) s += part[(size_t)q * partStride + idx];
    float z = __bfloat162float(zh[(size_t)c * M + m]) + __bfloat162float(zl[(size_t)c * M + m]);
    float dv = rsqrtf(deg[m] + 2.f);
    float v = dv * (s + 2.f * z) + bias[c];
    if (relu) v = fmaxf(v, 0.f);
    Y[idx] = v;
    if (p) {
        __shared__ float red[8];
        float d = v * p[c];
#pragma unroll
        for (int o = 16; o; o >>= 1) d += __shfl_down_sync(0xffffffffu, d, o);
        if ((c & 31) == 0) red[c >> 5] = d;
        __syncthreads();
        if (c < 8) {
            float a = red[c];
#pragma unroll
            for (int o = 4; o; o >>= 1) a += __shfl_down_sync(0xffu, a, o);
            if (c == 0) scout[m] = a;
        }
    }
}

// ---------------- shared tile loader (bf16, cp.async) ----------------
template <int G>
__device__ __forceinline__ void ld_tile(const bf16* __restrict__ src, int ld,
                                        int row0, int k0, uint16_t* dst, int tid,
                                        const int* __restrict__ pm) {
#pragma unroll
    for (int i = 0; i < 2; i++) {
        int s = tid + i * 256;
        int r = s >> 2, c8 = (s & 3) * 8;
        int row = row0 + r;
        if (G) row = pm[row];
        const bf16* g = src + (size_t)row * ld + k0 + c8;
        uint32_t sm = (uint32_t)__cvta_generic_to_shared(dst + r * 40 + c8);
        asm volatile("cp.async.ca.shared.global [%0], [%1], 16;\n" ::"r"(sm), "l"(g));
    }
}

// ---------------- MMA compute helper ----------------
__device__ __forceinline__ void mma_block(const uint16_t* Asb, const uint16_t* Bsb,
                                          int ks, int g, int tg, int wm, int wn,
                                          float acc[4][4][4]) {
    uint32_t af[4][4], bfr[4][2];
    const int kc = ks + 2 * tg;
#pragma unroll
    for (int mf = 0; mf < 4; mf++) {
        int m = wm * 64 + mf * 16 + g;
        af[mf][0] = *(const uint32_t*)&Asb[m * 40 + kc];
        af[mf][1] = *(const uint32_t*)&Asb[(m + 8) * 40 + kc];
        af[mf][2] = *(const uint32_t*)&Asb[m * 40 + kc + 8];
        af[mf][3] = *(const uint32_t*)&Asb[(m + 8) * 40 + kc + 8];
    }
#pragma unroll
    for (int nf = 0; nf < 4; nf++) {
        int n = wn * 32 + nf * 8 + g;
        bfr[nf][0] = *(const uint32_t*)&Bsb[n * 40 + kc];
        bfr[nf][1] = *(const uint32_t*)&Bsb[n * 40 + kc + 8];
    }
#pragma unroll
    for (int mf = 0; mf < 4; mf++)
#pragma unroll
        for (int nf = 0; nf < 4; nf++)
            asm volatile(
                "mma.sync.aligned.m16n8k16.row.col.f32.bf16.bf16.f32 "
                "{%0,%1,%2,%3},{%4,%5,%6,%7},{%8,%9},{%0,%1,%2,%3};"
                : "+f"(acc[mf][nf][0]), "+f"(acc[mf][nf][1]),
                  "+f"(acc[mf][nf][2]), "+f"(acc[mf][nf][3])
                : "r"(af[mf][0]), "r"(af[mf][1]), "r"(af[mf][2]),
                  "r"(af[mf][3]), "r"(bfr[nf][0]), "r"(bfr[nf][1]));
}

// ---------------- bf16-operand GEMM, 3-STAGE pipeline ----------------
template <int NPROD, int G>
__global__ void __launch_bounds__(256, 2) mma_gemm(
    const bf16* __restrict__ A0p, int lda,
    const bf16* __restrict__ B0p, const bf16* __restrict__ B1p, int ldb,
    float* __restrict__ Cp, int ldc, int ksplit, size_t partStride,
    const int* __restrict__ pm) {
    constexpr int PB = (NPROD >= 2) ? 2 : 1;
    constexpr int TS = 128 * 40;            // u16 per tile
    constexpr int SS = (1 + PB) * TS;       // u16 per stage
    extern __shared__ __align__(16) uint16_t sh[];

    const int tid = threadIdx.x;
    const int lane = tid & 31, warp = tid >> 5;
    const int g = lane >> 2, tg = lane & 3;
    const int wm = warp >> 2, wn = warp & 3;
    const int m0 = blockIdx.y * 128, j0 = blockIdx.x * 128;

    float acc[4][4][4];
#pragma unroll
    for (int a = 0; a < 4; a++)
#pragma unroll
        for (int b = 0; b < 4; b++)
#pragma unroll
            for (int e = 0; e < 4; e++) acc[a][b][e] = 0.f;

    auto load_stage = [&](int st, int k0) {
        ld_tile<G>(A0p, lda, m0, k0, sh + st * SS, tid, pm);
        ld_tile<G>(B0p, ldb, j0, k0, sh + st * SS + TS, tid, pm);
        if (PB == 2) ld_tile<G>(B1p, ldb, j0, k0, sh + st * SS + 2 * TS, tid, pm);
        asm volatile("cp.async.commit_group;\n" ::);
    };

    const int kb = blockIdx.z * ksplit;
    const int nt = ksplit / 32;

    load_stage(0, kb);
    if (nt > 1) load_stage(1, kb + 32);
    int st = 0;
    for (int it = 0; it < nt; it++) {
        if (it + 1 < nt)
            asm volatile("cp.async.wait_group 1;\n" ::);
        else
            asm volatile("cp.async.wait_group 0;\n" ::);
        __syncthreads();
        if (it + 2 < nt) load_stage((st + 2) % 3, kb + (it + 2) * 32);
        const uint16_t* As = sh + st * SS;
        const uint16_t* Bs0 = As + TS;
#pragma unroll
        for (int ks = 0; ks < 32; ks += 16)
            mma_block(As, Bs0, ks, g, tg, wm, wn, acc);
        if (PB == 2) {
            const uint16_t* Bs1 = As + 2 * TS;
#pragma unroll
            for (int ks = 0; ks < 32; ks += 16)
                mma_block(As, Bs1, ks, g, tg, wm, wn, acc);
        }
        st = (st + 1) % 3;
    }

#pragma unroll
    for (int mf = 0; mf < 4; mf++)
#pragma unroll
        for (int nf = 0; nf < 4; nf++)
#pragma unroll
            for (int e = 0; e < 4; e++) {
                int m = m0 + wm * 64 + mf * 16 + g + (e >> 1) * 8;
                int c = j0 + wn * 32 + nf * 8 + 2 * tg + (e & 1);
                Cp[(size_t)blockIdx.z * partStride + (size_t)m * ldc + c] = acc[mf][nf][e];
            }
}

// ---------------- fused XW GEMM (proven pipeline) ----------------
// IN=1: A = Xsrc[m][k]
// IN=2: A = Xsrc[idx[m]][k] * tanh(s[idx[m]]*pn)
// IN=3: A = Xsrc[m][k] + (idx[m]>=0 ? xcur[idx[m]][k] : 0)
// MODE=1: z = rsqrt(scl[m]+2)*acc -> zhi/zlo transposed [c*n+m]
// MODE=2: z = scl[m]*acc -> fp32 [m*256+c]
template <int MODE, int IN>
__global__ void __launch_bounds__(256, 2) xw_gemm(
    const float* __restrict__ Xsrc, int K,
    const float* __restrict__ xcur, const int* __restrict__ idx,
    const float* __restrict__ s, const float* __restrict__ pn,
    const bf16* __restrict__ Bh, const bf16* __restrict__ Bl,
    void* __restrict__ Cp, void* __restrict__ C2p, int n,
    const float* __restrict__ scl) {
    extern __shared__ __align__(16) uint16_t sh[];
    uint16_t* Ahi = sh;
    uint16_t* Alo = sh + 5120;
    uint16_t* Bst = sh + 2 * 5120;

    const int tid = threadIdx.x;
    const int lane = tid & 31, warp = tid >> 5;
    const int g = lane >> 2, tg = lane & 3;
    const int wm = warp >> 2, wn = warp & 3;
    const int m0 = blockIdx.y * 128, j0 = blockIdx.x * 128;

    float acc[4][4][4];
#pragma unroll
    for (int a = 0; a < 4; a++)
#pragma unroll
        for (int b = 0; b < 4; b++)
#pragma unroll
            for (int e = 0; e < 4; e++) acc[a][b][e] = 0.f;

    auto loadB = [&](int st, int k0) {
        ld_tile<0>(Bh, K, j0, k0, Bst + st * 2 * 5120, tid, nullptr);
        ld_tile<0>(Bl, K, j0, k0, Bst + (st * 2 + 1) * 5120, tid, nullptr);
        asm volatile("cp.async.commit_group;\n" ::);
    };

    const int arow = tid >> 1;
    const int coff = (tid & 1) * 16;
    const int m = m0 + arow;
    int srow = 0;
    float gate = 1.f;
    if (IN == 2) {
        srow = idx[m];
        gate = tanhf(s[srow] * pn[0]);
    } else if (IN == 3) {
        srow = idx[m];
    }

    const int nt = K / 32;
    loadB(0, 0);
    for (int it = 0; it < nt; it++) {
        float av[16];
        int kb = it * 32 + coff;
        if (IN == 1) {
#pragma unroll
            for (int q = 0; q < 4; q++) {
                float4 v = *(const float4*)(Xsrc + (size_t)m * K + kb + q * 4);
                av[q * 4] = v.x; av[q * 4 + 1] = v.y; av[q * 4 + 2] = v.z; av[q * 4 + 3] = v.w;
            }
        } else if (IN == 2) {
#pragma unroll
            for (int q = 0; q < 4; q++) {
                float4 v = *(const float4*)(Xsrc + (size_t)srow * K + kb + q * 4);
                av[q * 4] = v.x * gate; av[q * 4 + 1] = v.y * gate;
                av[q * 4 + 2] = v.z * gate; av[q * 4 + 3] = v.w * gate;
            }
        } else {
#pragma unroll
            for (int q = 0; q < 4; q++) {
                float4 v = *(const float4*)(Xsrc + (size_t)m * K + kb + q * 4);
                av[q * 4] = v.x; av[q * 4 + 1] = v.y; av[q * 4 + 2] = v.z; av[q * 4 + 3] = v.w;
            }
            if (srow >= 0) {
#pragma unroll
                for (int q = 0; q < 4; q++) {
                    float4 v = *(const float4*)(xcur + (size_t)srow * K + kb + q * 4);
                    av[q * 4] += v.x; av[q * 4 + 1] += v.y;
                    av[q * 4 + 2] += v.z; av[q * 4 + 3] += v.w;
                }
            }
        }
        if (it + 1 < nt) {
            loadB((it + 1) & 1, (it + 1) * 32);
            asm volatile("cp.async.wait_group 1;\n" ::);
        } else {
            asm volatile("cp.async.wait_group 0;\n" ::);
        }
        __syncthreads();
#pragma unroll
        for (int e = 0; e < 16; e++) {
            float v = av[e];
            bf16 h = __float2bfloat16(v);
            Ahi[arow * 40 + coff + e] = __bfloat16_as_ushort(h);
            Alo[arow * 40 + coff + e] =
                __bfloat16_as_ushort(__float2bfloat16(v - __bfloat162float(h)));
        }
        __syncthreads();
        const uint16_t* Bhi_s = Bst + (it & 1) * 2 * 5120;
        const uint16_t* Blo_s = Bhi_s + 5120;
#pragma unroll
        for (int ks = 0; ks < 32; ks += 16) {
            mma_block(Ahi, Bhi_s, ks, g, tg, wm, wn, acc);
            mma_block(Ahi, Blo_s, ks, g, tg, wm, wn, acc);
            mma_block(Alo, Bhi_s, ks, g, tg, wm, wn, acc);
        }
    }

#pragma unroll
    for (int mf = 0; mf < 4; mf++)
#pragma unroll
        for (int nf = 0; nf < 4; nf++)
#pragma unroll
            for (int e = 0; e < 4; e++) {
                int mm = m0 + wm * 64 + mf * 16 + g + (e >> 1) * 8;
                int c = j0 + wn * 32 + nf * 8 + 2 * tg + (e & 1);
                float v = acc[mf][nf][e];
                if (MODE == 1) {
                    v *= rsqrtf(scl[mm] + 2.f);
                    bf16 h = __float2bfloat16(v);
                    ((bf16*)Cp)[(size_t)c * n + mm] = h;
                    ((bf16*)C2p)[(size_t)c * n + mm] =
                        __float2bfloat16(v - __bfloat162float(h));
                } else {
                    ((float*)Cp)[(size_t)mm * 256 + c] = v * scl[mm];
                }
            }
}

// ---------------- host orchestration ----------------
#define SYM(p, s)                     \
    do {                              \
        void* _t = nullptr;           \
        cudaGetSymbolAddress(&_t, s); \
        p = (decltype(p))_t;          \
    } while (0)

extern "C" void kernel_launch(void* const* d_in, const int* in_sizes, int n_in,
                              void* d_out, int out_size) {
    const float* x_in = (const float*)d_in[0];
    const int* ei     = (const int*)d_in[1];
    const float* w_d0 = (const float*)d_in[3];
    const float* b_d0 = (const float*)d_in[4];
    const float* w_d  = (const float*)d_in[5];
    const float* b_d  = (const float*)d_in[6];
    const float* p_at = (const float*)d_in[7];
    const float* w_u  = (const float*)d_in[8];
    const float* b_u  = (const float*)d_in[9];
    float* out = (float*)d_out;
    const int E = in_sizes[1] / 2;

    bf16 *A1, *A2, *A3, *AT1, *AT2, *AT3, *WH, *WL, *zhi, *zlo;
    float *X0, *X1, *X2, *Xc, *Cpart, *zf, *A1f, *dinv0, *fil0, *sc, *pns, *mpart;
    int *zblk, *perm, *colmap, *rpi, *rpo, *cii, *cio, *curi, *curo;
    SYM(A1, g_A1);   SYM(A2, g_A2);   SYM(A3, g_A3);
    SYM(AT1, g_AT1); SYM(AT2, g_AT2); SYM(AT3, g_AT3);
    SYM(WH, g_WH);   SYM(WL, g_WL);
    SYM(zhi, g_zhi); SYM(zlo, g_zlo);
    SYM(X0, g_X0);   SYM(X1, g_X1);   SYM(X2, g_X2);
    SYM(Xc, g_Xc);   SYM(Cpart, g_Cpart);
    SYM(zf, g_z);    SYM(A1f, g_A1f);
    SYM(zblk, g_zblk);
    SYM(dinv0, g_dinv0); SYM(fil0, g_fil0);
    SYM(sc, g_s);    SYM(pns, g_pns); SYM(mpart, g_mpart);
    SYM(perm, g_perm); SYM(colmap, g_colmap);
    SYM(rpi, g_rpi); SYM(rpo, g_rpo); SYM(cii, g_cii); SYM(cio, g_cio);
    SYM(curi, g_curi); SYM(curo, g_curo);
    int* cnt = zblk;
    float* deg = (float*)(zblk + 3 * N0);

    cudaFuncSetAttribute(mma_gemm<2, 0>, cudaFuncAttributeMaxDynamicSharedMemorySize, 92160);
    cudaFuncSetAttribute(mma_gemm<1, 1>, cudaFuncAttributeMaxDynamicSharedMemorySize, 61440);
    cudaFuncSetAttribute(xw_gemm<2, 1>, cudaFuncAttributeMaxDynamicSharedMemorySize, 61440);
    cudaFuncSetAttribute(xw_gemm<2, 3>, cudaFuncAttributeMaxDynamicSharedMemorySize, 61440);
    cudaFuncSetAttribute(xw_gemm<1, 2>, cudaFuncAttributeMaxDynamicSharedMemorySize, 61440);
    cudaFuncSetAttribute(xw_gemm<1, 3>, cudaFuncAttributeMaxDynamicSharedMemorySize, 61440);

    bf16* Alv[4] = {nullptr, A1, A2, A3};
    bf16* ATlv[4] = {nullptr, AT1, AT2, AT3};
    float* Xs[3] = {X0, X1, X2};
    const int ns[4] = {4096, 2048, 1024, 512};

    // ---- fused setup ----
    setup_all<<<cdiv(NWSPLIT + 10 * N0, 256), 256>>>(w_d0, w_d, w_u, WH, WL, zblk, colmap);
    count_deg<<<cdiv(E, 256), 256>>>(ei, E, cnt);
    scan_build<<<1, 1024>>>(cnt, rpi, rpo, curi, curo, dinv0, fil0, p_at, pns);
    fill_csr<<<cdiv(E, 256), 256>>>(ei, E, curi, curo, cii, cio);

    // dense GCN levels 1..3 (full score fused into reduce when pnext)
    auto gcn = [&](int lvl, int slot, const float* Xsrc, const int* pidx, int IN,
                   const float* bias, float* Y, int relu, const float* pnext) {
        int n = ns[lvl];
        if (IN == 2)
            xw_gemm<1, 2><<<dim3(2, n / 128), 256, 61440>>>(
                Xsrc, 256, nullptr, pidx, sc, pns + (lvl - 1), WH + slot * 65536,
                WL + slot * 65536, zhi, zlo, n, deg + lvl * N0);
        else
            xw_gemm<1, 3><<<dim3(2, n / 128), 256, 61440>>>(
                Xsrc, 256, Xc, pidx, nullptr, nullptr, WH + slot * 65536,
                WL + slot * 65536, zhi, zlo, n, deg + lvl * N0);
        mma_gemm<2, 0><<<dim3(2, n / 128, 8), 256, 92160>>>(
            ATlv[lvl], n, zhi, zlo, n, Cpart, 256, n / 8, (size_t)n * 256, nullptr);
        reduce_gcn<<<n, 256>>>(Cpart, 8, n * 256, n, zhi, zlo, deg + lvl * N0,
                               bias, Y, relu, pnext, sc);
    };

    // ---- level-0 down GCN (score fused into spmv) ----
    xw_gemm<2, 1><<<dim3(2, N0 / 128), 256, 61440>>>(
        x_in, 128, nullptr, nullptr, nullptr, nullptr, WH, WL, zf, nullptr, N0, dinv0);
    spmv_gcn<<<N0 / 8, 256>>>(rpi, cii, zf, dinv0, fil0, b_d0, X0, 1, p_at, sc, nullptr);

    // ---- down path ----
    for (int i = 0; i < 3; i++) {
        int n = ns[i], k = ns[i + 1];
        int* pm = perm + i * 2048;
        int* cm = colmap + i * N0;

        if (i == 0) topk_select<4096><<<1, 1024>>>(sc, k, pm, cm);
        else if (i == 1) topk_select<2048><<<1, 1024>>>(sc, k, pm, cm);
        else topk_select<1024><<<1, 1024>>>(sc, k, pm, cm);

        if (i == 0) {
            sparse_augment<<<k, 256>>>(pm, cm, rpo, cio, A1f, k);
            finalize_A1<<<dim3(k / 64, k / 64), 256>>>(A1f, A1, AT1, deg + N0, k);
        } else {
            mma_gemm<1, 1><<<dim3(k / 128, k / 128, 4), 256, 61440>>>(
                Alv[i], n, ATlv[i], nullptr, n, A1f, k, n / 4, (size_t)k * k, pm);
            finalize_aug<<<dim3(k / 64, k / 64), 256>>>(A1f, Alv[i], pm, k, n,
                                                        Alv[i + 1], ATlv[i + 1],
                                                        deg + (i + 1) * N0);
        }

        float* Y = (i < 2) ? Xs[i + 1] : Xc;
        const float* pnext = (i < 2) ? (p_at + (i + 1) * CH) : nullptr;
        gcn(i + 1, 1 + i, Xs[i], pm, 2, b_d + i * CH, Y, 1, pnext);
    }

    // ---- up path ----
    for (int i = 0; i < 3; i++) {
        int j = 2 - i;
        if (j == 0) {
            xw_gemm<2, 3><<<dim3(2, N0 / 128), 256, 61440>>>(
                X0, 256, Xc, colmap, nullptr, nullptr,
                WH + (4 + i) * 65536, WL + (4 + i) * 65536, zf, nullptr, N0, dinv0);
            spmv_gcn<<<N0 / 8, 256>>>(rpi, cii, zf, dinv0, fil0, b_u + i * CH, Xc, 0,
                                      nullptr, nullptr, mpart);
        } else {
            gcn(j, 4 + i, Xs[j], colmap + j * N0, 3, b_u + i * CH, Xc, 1, nullptr);
        }
    }

    mean_final<<<1, 256>>>(mpart, out);
}